// round 2
// baseline (speedup 1.0000x reference)
#include <cuda_runtime.h>
#include <math.h>

#define MTOK  32768
#define HDIM  256
#define SLOTS 4096
#define KVW   768

#define PADK 68    // row stride (floats) for k-major 64-wide tiles
#define PADV 264   // row stride for row-major V tile

// ---------------- scratch (static device memory; no allocation) ----------------
__device__ float g_xproj [MTOK*HDIM];
__device__ float g_query [MTOK*HDIM];
__device__ float g_memout[MTOK*HDIM];
__device__ float g_kvbuf [MTOK*KVW];
__device__ float g_opre  [MTOK*HDIM];
__device__ float g_gk    [SLOTS*HDIM];
__device__ float g_gv    [SLOTS*HDIM];
__device__ float g_gcnt  [SLOTS];

// ---------------- zero the scatter accumulators (every launch: replay-safe) ----
__global__ void zero_kernel()
{
    int i = blockIdx.x * blockDim.x + threadIdx.x;
    if (i < SLOTS*HDIM) { g_gk[i] = 0.f; g_gv[i] = 0.f; }
    if (i < SLOTS) g_gcnt[i] = 0.f;
}

// ---------------- SGEMM: C[M,N] = concat(A0,A1)[M,K] @ B[K,N] + bias -----------
// 128x128 tile, BK=8, 256 threads, 8x8 per thread. All dims are multiples, no guards.
__global__ __launch_bounds__(256)
void sgemm128(const float* __restrict__ A0, const float* __restrict__ A1,
              int K, int K0,
              const float* __restrict__ B, const float* __restrict__ bias,
              float* __restrict__ C, int N)
{
    __shared__ float As[8][128];
    __shared__ float Bs[8][128];
    const int tid  = threadIdx.x;
    const int bn   = blockIdx.x, bm = blockIdx.y;
    const int arow = tid >> 1;
    const int acol = (tid & 1) << 2;
    const int brow = tid >> 5;
    const int bcol = (tid & 31) << 2;
    const int tx   = tid & 15, ty = tid >> 4;
    const int rowg = bm * 128 + arow;
    const int colg = bn * 128 + bcol;

    float acc[8][8];
#pragma unroll
    for (int i = 0; i < 8; i++)
#pragma unroll
        for (int j = 0; j < 8; j++) acc[i][j] = 0.f;

    for (int k0 = 0; k0 < K; k0 += 8) {
        const float* Asrc; int lda, kk;
        if (k0 < K0) { Asrc = A0; lda = K0;     kk = k0;      }
        else         { Asrc = A1; lda = K - K0; kk = k0 - K0; }
        float4 av = *(const float4*)(Asrc + (size_t)rowg * lda + kk + acol);
        float4 bv = *(const float4*)(B    + (size_t)(k0 + brow) * N + colg);
        __syncthreads();
        As[acol+0][arow] = av.x;
        As[acol+1][arow] = av.y;
        As[acol+2][arow] = av.z;
        As[acol+3][arow] = av.w;
        *(float4*)&Bs[brow][bcol] = bv;
        __syncthreads();
#pragma unroll
        for (int k = 0; k < 8; k++) {
            float a[8], b[8];
            *(float4*)&a[0] = *(const float4*)&As[k][ty*8];
            *(float4*)&a[4] = *(const float4*)&As[k][ty*8+4];
            *(float4*)&b[0] = *(const float4*)&Bs[k][tx*8];
            *(float4*)&b[4] = *(const float4*)&Bs[k][tx*8+4];
#pragma unroll
            for (int i = 0; i < 8; i++)
#pragma unroll
                for (int j = 0; j < 8; j++)
                    acc[i][j] += a[i] * b[j];
        }
    }
    const int crow = bm * 128 + ty * 8;
    const int ccol = bn * 128 + tx * 8;
    float bb[8];
#pragma unroll
    for (int j = 0; j < 8; j++) bb[j] = bias ? bias[ccol + j] : 0.f;
#pragma unroll
    for (int i = 0; i < 8; i++) {
        float4 v0, v1;
        v0.x = acc[i][0]+bb[0]; v0.y = acc[i][1]+bb[1]; v0.z = acc[i][2]+bb[2]; v0.w = acc[i][3]+bb[3];
        v1.x = acc[i][4]+bb[4]; v1.y = acc[i][5]+bb[5]; v1.z = acc[i][6]+bb[6]; v1.w = acc[i][7]+bb[7];
        float* cp = C + (size_t)(crow + i) * N + ccol;
        *(float4*)cp       = v0;
        *(float4*)(cp + 4) = v1;
    }
}

// ---------------- block-wide sum over 256 threads -------------------------------
__device__ __forceinline__ float block_sum_256(float v, float* red)
{
#pragma unroll
    for (int o = 16; o > 0; o >>= 1) v += __shfl_xor_sync(0xffffffffu, v, o);
    if ((threadIdx.x & 31) == 0) red[threadIdx.x >> 5] = v;
    __syncthreads();
    float t = 0.f;
#pragma unroll
    for (int i = 0; i < 8; i++) t += red[i];
    __syncthreads();
    return t;
}

// ---------------- in-place LayerNorm + exact GELU (W = 256 or 768) --------------
__global__ __launch_bounds__(256)
void ln_gelu_kernel(float* __restrict__ X, const float* __restrict__ gm,
                    const float* __restrict__ bt, int W)
{
    __shared__ float red[8];
    const int row = blockIdx.x, tid = threadIdx.x;
    float* xr = X + (size_t)row * W;
    const int cnt = W >> 8;        // 1 or 3
    float vals[3];
    float s = 0.f;
    for (int i = 0; i < cnt; i++) { vals[i] = xr[tid + (i << 8)]; s += vals[i]; }
    float mean = block_sum_256(s, red) / (float)W;
    float sq = 0.f;
    for (int i = 0; i < cnt; i++) { float d = vals[i] - mean; sq += d * d; }
    float var  = block_sum_256(sq, red) / (float)W;
    float rstd = rsqrtf(var + 1e-5f);
    for (int i = 0; i < cnt; i++) {
        int c = tid + (i << 8);
        float t = (vals[i] - mean) * rstd * gm[c] + bt[c];
        xr[c] = 0.5f * t * (1.f + erff(t * 0.70710678f));
    }
}

// ---------------- shared tile helpers for score GEMMs ---------------------------
// load 64 rows x 256 cols (row-major, given stride) into k-major tile dst[k][r]
__device__ __forceinline__ void load_kmajor64(float* dst, const float* src, int stride)
{
    const int tid = threadIdx.x;
#pragma unroll
    for (int i = 0; i < 16; i++) {
        int lin = tid + (i << 8);
        int r   = lin >> 6;
        int kq  = (lin & 63) << 2;
        float4 v = *(const float4*)(src + (size_t)r * stride + kq);
        dst[(kq+0)*PADK + r] = v.x;
        dst[(kq+1)*PADK + r] = v.y;
        dst[(kq+2)*PADK + r] = v.z;
        dst[(kq+3)*PADK + r] = v.w;
    }
}

// ss[64][PADK] = (qs^T kt) * scale ; 256 threads, 4x4 per thread
__device__ __forceinline__ void score_tile(const float* qs, const float* kt,
                                           float* ss, float scale)
{
    const int tid = threadIdx.x;
    const int stx = tid & 15, sty = tid >> 4;
    float acc[4][4];
#pragma unroll
    for (int i = 0; i < 4; i++)
#pragma unroll
        for (int j = 0; j < 4; j++) acc[i][j] = 0.f;
    const float* qp = qs + sty * 4;
    const float* kp = kt + stx * 4;
#pragma unroll 4
    for (int k = 0; k < 256; k++) {
        float4 a = *(const float4*)(qp + k * PADK);
        float4 b = *(const float4*)(kp + k * PADK);
        acc[0][0] += a.x*b.x; acc[0][1] += a.x*b.y; acc[0][2] += a.x*b.z; acc[0][3] += a.x*b.w;
        acc[1][0] += a.y*b.x; acc[1][1] += a.y*b.y; acc[1][2] += a.y*b.z; acc[1][3] += a.y*b.w;
        acc[2][0] += a.z*b.x; acc[2][1] += a.z*b.y; acc[2][2] += a.z*b.z; acc[2][3] += a.z*b.w;
        acc[3][0] += a.w*b.x; acc[3][1] += a.w*b.y; acc[3][2] += a.w*b.z; acc[3][3] += a.w*b.w;
    }
#pragma unroll
    for (int i = 0; i < 4; i++) {
        float4 v;
        v.x = acc[i][0]*scale; v.y = acc[i][1]*scale; v.z = acc[i][2]*scale; v.w = acc[i][3]*scale;
        *(float4*)(ss + (sty*4 + i) * PADK + stx*4) = v;
    }
}

// ---------------- fused flash attention over memory slots -----------------------
// per block: 64 query rows; loops S in 64-slot tiles; online softmax; o = attn @ V
__global__ __launch_bounds__(256)
void attn_kernel(const float* __restrict__ Q, const float* __restrict__ Km,
                 const float* __restrict__ Vm,
                 float* __restrict__ O, float* __restrict__ surp)
{
    extern __shared__ float sm[];
    float* qs = sm;                       // [256][PADK]   k-major query tile
    float* kv = sm + 256 * PADK;          // K tile (k-major) / V tile (row-major) union
    float* ss = sm + 2 * 256 * PADK;      // [64][PADK]    score / prob tile
    const int tid  = threadIdx.x;
    const int row0 = blockIdx.x * 64;
    load_kmajor64(qs, Q + (size_t)row0 * HDIM, HDIM);

    const int srow = tid >> 2, part = tid & 3;  // 64 rows x 4 column-parts
    float4 oacc[16];
#pragma unroll
    for (int i = 0; i < 16; i++) oacc[i] = make_float4(0.f, 0.f, 0.f, 0.f);
    float run_m = -INFINITY, run_l = 0.f;

    for (int s0 = 0; s0 < SLOTS; s0 += 64) {
        __syncthreads();                                   // kv/ss reuse fence
        load_kmajor64(kv, Km + (size_t)s0 * HDIM, HDIM);   // K tile
        __syncthreads();
        score_tile(qs, kv, ss, 0.0625f);                   // 1/sqrt(256)
        __syncthreads();
        // stage V tile (kv buffer is free now) while doing the softmax update
#pragma unroll
        for (int i = 0; i < 16; i++) {
            int lin = tid + (i << 8);
            int j   = lin >> 6;
            int cq  = (lin & 63) << 2;
            *(float4*)(kv + j * PADV + cq) = *(const float4*)(Vm + (size_t)(s0 + j) * HDIM + cq);
        }
        float* sr = ss + srow * PADK + part * 16;
        float mloc = -INFINITY;
#pragma unroll
        for (int t = 0; t < 16; t++) mloc = fmaxf(mloc, sr[t]);
        mloc = fmaxf(mloc, __shfl_xor_sync(0xffffffffu, mloc, 1));
        mloc = fmaxf(mloc, __shfl_xor_sync(0xffffffffu, mloc, 2));
        float nm    = fmaxf(run_m, mloc);
        float alpha = expf(run_m - nm);
        float ls = 0.f;
#pragma unroll
        for (int t = 0; t < 16; t++) { float p = expf(sr[t] - nm); sr[t] = p; ls += p; }
        ls += __shfl_xor_sync(0xffffffffu, ls, 1);
        ls += __shfl_xor_sync(0xffffffffu, ls, 2);
        run_l = run_l * alpha + ls;
        run_m = nm;
#pragma unroll
        for (int i = 0; i < 16; i++) {
            oacc[i].x *= alpha; oacc[i].y *= alpha; oacc[i].z *= alpha; oacc[i].w *= alpha;
        }
        __syncthreads();
        // o += p @ V ; thread covers columns part*4 + 16*i (bank-conflict-free)
        const float* ssrow = ss + srow * PADK;
        const float* vbase = kv + part * 4;
#pragma unroll 2
        for (int j = 0; j < 64; j++) {
            float p = ssrow[j];
            const float* vr = vbase + j * PADV;
#pragma unroll
            for (int i = 0; i < 16; i++) {
                float4 v = *(const float4*)(vr + (i << 4));
                oacc[i].x += p * v.x; oacc[i].y += p * v.y;
                oacc[i].z += p * v.z; oacc[i].w += p * v.w;
            }
        }
    }
    float inv = 1.f / run_l;
    float* orow = O + (size_t)(row0 + srow) * HDIM + part * 4;
#pragma unroll
    for (int i = 0; i < 16; i++) {
        float4 v;
        v.x = oacc[i].x*inv; v.y = oacc[i].y*inv; v.z = oacc[i].z*inv; v.w = oacc[i].w*inv;
        *(float4*)(orow + (i << 4)) = v;
    }
    if (part == 0) surp[row0 + srow] = 1.f - inv;  // 1 - max(attn) = 1 - 1/Z
}

// ---------------- wsim argmax + surprise-gated scatter write ---------------------
__global__ __launch_bounds__(256)
void write_kernel(const float* __restrict__ KV, const float* __restrict__ Km,
                  const float* __restrict__ surp)
{
    extern __shared__ float sm[];
    float* qs = sm;
    float* kt = sm + 256 * PADK;
    float* ss = sm + 2 * 256 * PADK;
    const int tid  = threadIdx.x;
    const int row0 = blockIdx.x * 64;
    load_kmajor64(qs, KV + (size_t)row0 * KVW, KVW);   // key_new = kv_lr[:, 0:256]
    const int srow = tid >> 2, part = tid & 3;
    float bv = -INFINITY; int bi = 0;

    for (int s0 = 0; s0 < SLOTS; s0 += 64) {
        __syncthreads();
        load_kmajor64(kt, Km + (size_t)s0 * HDIM, HDIM);
        __syncthreads();
        score_tile(qs, kt, ss, 1.0f);                  // no 1/sqrt(H) here
        __syncthreads();
        const float* sr = ss + srow * PADK + part * 16;
#pragma unroll
        for (int t = 0; t < 16; t++) {
            float v = sr[t];
            if (v > bv) { bv = v; bi = s0 + part * 16 + t; }   // first-max within thread
        }
    }
    // combine across the 4 lanes of this row, tie -> lowest slot index (jnp.argmax)
#pragma unroll
    for (int o = 1; o < 4; o <<= 1) {
        float ov = __shfl_xor_sync(0xffffffffu, bv, o);
        int   oi = __shfl_xor_sync(0xffffffffu, bi, o);
        if (ov > bv || (ov == bv && oi < bi)) { bv = ov; bi = oi; }
    }
    const int   token = row0 + srow;
    const float gate  = surp[token];
    const float* kr   = KV + (size_t)token * KVW;
    const int c0 = part * 64;
    for (int c = 0; c < 64; c++) {
        atomicAdd(&g_gk[bi * HDIM + c0 + c], gate * kr[c0 + c]);          // key_new
        atomicAdd(&g_gv[bi * HDIM + c0 + c], gate * kr[HDIM + c0 + c]);   // value_new
    }
    if (part == 0) atomicAdd(&g_gcnt[bi], gate);
}

// ---------------- DGD-style gated memory update ---------------------------------
__global__ void memupd_kernel(const float* __restrict__ Km, const float* __restrict__ Vm,
                              float* __restrict__ Kout, float* __restrict__ Vout)
{
    int i = blockIdx.x * blockDim.x + threadIdx.x;   // exactly SLOTS*HDIM threads
    float cnt = g_gcnt[i >> 8];
    float k = Km[i], v = Vm[i];
    Kout[i] = k + 0.1f * (g_gk[i] - cnt * k);
    Vout[i] = v + 0.1f * (g_gv[i] - cnt * v);
}

// ---------------- final double LayerNorm ----------------------------------------
__global__ __launch_bounds__(256)
void final_ln_kernel(const float* __restrict__ opre, const float* __restrict__ xproj,
                     const float* __restrict__ go, const float* __restrict__ beo,
                     const float* __restrict__ g1, const float* __restrict__ be1,
                     float* __restrict__ out)
{
    __shared__ float red[8];
    const int row = blockIdx.x, tid = threadIdx.x;
    float v    = opre[(size_t)row * HDIM + tid];
    float mean = block_sum_256(v, red) * (1.f / 256.f);
    float d    = v - mean;
    float var  = block_sum_256(d * d, red) * (1.f / 256.f);
    float t    = d * rsqrtf(var + 1e-5f) * go[tid] + beo[tid];
    float u    = t + xproj[(size_t)row * HDIM + tid];
    float m2   = block_sum_256(u, red) * (1.f / 256.f);
    float d2   = u - m2;
    float v2   = block_sum_256(d2 * d2, red) * (1.f / 256.f);
    out[(size_t)row * HDIM + tid] = d2 * rsqrtf(v2 + 1e-5f) * g1[tid] + be1[tid];
}

// ---------------- lr = mean(sigmoid(lr_logit)) ----------------------------------
__global__ __launch_bounds__(256)
void lr_kernel(const float* __restrict__ KV, float* __restrict__ lr)
{
    __shared__ float red[8];
    const int row = blockIdx.x, tid = threadIdx.x;
    float x = KV[(size_t)row * KVW + 512 + tid];
    float s = 1.f / (1.f + expf(-x));
    float tot = block_sum_256(s, red);
    if (tid == 0) lr[row] = tot * (1.f / 256.f);
}

// =================================================================================
extern "C" void kernel_launch(void* const* d_in, const int* in_sizes, int n_in,
                              void* d_out, int out_size)
{
    const float* x    = (const float*)d_in[0];
    const float* W_in = (const float*)d_in[1];
    const float* b_in = (const float*)d_in[2];
    const float* W_q  = (const float*)d_in[3];
    const float* b_q  = (const float*)d_in[4];
    const float* gq   = (const float*)d_in[5];
    const float* beq  = (const float*)d_in[6];
    const float* Km   = (const float*)d_in[7];
    const float* Vm   = (const float*)d_in[8];
    const float* W_kv = (const float*)d_in[9];
    const float* b_kv = (const float*)d_in[10];
    const float* gkv  = (const float*)d_in[11];
    const float* bekv = (const float*)d_in[12];
    const float* W_o  = (const float*)d_in[13];
    const float* b_o  = (const float*)d_in[14];
    const float* go   = (const float*)d_in[15];
    const float* beo  = (const float*)d_in[16];
    const float* g1   = (const float*)d_in[17];
    const float* be1  = (const float*)d_in[18];

    // output tuple layout: out, K_new, V_new, surprise, lr
    float* out    = (float*)d_out;
    float* o_out  = out;
    float* k_out  = out + 8388608;    // 32768*256
    float* v_out  = out + 9437184;    // + 4096*256
    float* s_out  = out + 10485760;   // + 4096*256
    float* lr_out = out + 10518528;   // + 32768

    float *p_xproj, *p_query, *p_memout, *p_kvbuf, *p_opre;
    cudaGetSymbolAddress((void**)&p_xproj,  g_xproj);
    cudaGetSymbolAddress((void**)&p_query,  g_query);
    cudaGetSymbolAddress((void**)&p_memout, g_memout);
    cudaGetSymbolAddress((void**)&p_kvbuf,  g_kvbuf);
    cudaGetSymbolAddress((void**)&p_opre,   g_opre);

    const int SMEMB = (256 * PADK * 2 + 64 * PADK) * 4;   // 156,672 B
    cudaFuncSetAttribute(attn_kernel,  cudaFuncAttributeMaxDynamicSharedMemorySize, SMEMB);
    cudaFuncSetAttribute(write_kernel, cudaFuncAttributeMaxDynamicSharedMemorySize, SMEMB);

    zero_kernel<<<4096, 256>>>();
    // x_proj = x @ W_in + b_in
    sgemm128<<<dim3(2, 256), 256>>>(x, nullptr, 256, 256, W_in, b_in, p_xproj, 256);
    // q_pre = x_proj @ W_q + b_q ; query = gelu(LN(q_pre))
    sgemm128<<<dim3(2, 256), 256>>>(p_xproj, nullptr, 256, 256, W_q, b_q, p_query, 256);
    ln_gelu_kernel<<<32768, 256>>>(p_query, gq, beq, 256);
    // mem_out, surprise
    attn_kernel<<<512, 256, SMEMB>>>(p_query, Km, Vm, p_memout, s_out);
    // kv_lr = gelu(LN(concat(x_proj, mem_out) @ W_kv + b_kv))
    sgemm128<<<dim3(6, 256), 256>>>(p_xproj, p_memout, 512, 256, W_kv, b_kv, p_kvbuf, 768);
    ln_gelu_kernel<<<32768, 256>>>(p_kvbuf, gkv, bekv, 768);
    lr_kernel<<<32768, 256>>>(p_kvbuf, lr_out);
    // argmax over wsim + gated scatter into gk/gv/gcnt
    write_kernel<<<512, 256, SMEMB>>>(p_kvbuf, Km, s_out);
    memupd_kernel<<<4096, 256>>>(Km, Vm, k_out, v_out);
    // out = LN(LN(combined @ W_o + b_o) + x_proj)
    sgemm128<<<dim3(2, 256), 256>>>(p_xproj, p_memout, 512, 256, W_o, b_o, p_opre, 256);
    final_ln_kernel<<<32768, 256>>>(p_opre, p_xproj, go, beo, g1, be1, o_out);
}

// round 4
// speedup vs baseline: 4.4214x; 4.4214x over previous
#include <cuda_runtime.h>
#include <cuda_bf16.h>
#include <math.h>
#include <stdint.h>

#define MTOK  32768
#define HDIM  256
#define SLOTS 4096
#define KVW   768

typedef __nv_bfloat16 bf16;

// ======================= static scratch (no allocation) ========================
__device__ float g_xproj [MTOK*HDIM];
__device__ float g_query [MTOK*HDIM];
__device__ float g_memout[MTOK*HDIM];
__device__ float g_kvbuf [MTOK*KVW];
__device__ float g_opre  [MTOK*HDIM];
__device__ float g_sim   [(size_t)MTOK*SLOTS];     // sim, then reused for wsim
__device__ float g_gk    [SLOTS*HDIM];
__device__ float g_gv    [SLOTS*HDIM];
__device__ float g_gcnt  [SLOTS];

__device__ bf16 g_xh [MTOK*HDIM], g_xl [MTOK*HDIM];
__device__ bf16 g_xph[MTOK*HDIM], g_xpl[MTOK*HDIM];
__device__ bf16 g_qh [MTOK*HDIM], g_ql [MTOK*HDIM];
__device__ bf16 g_moh[MTOK*HDIM], g_mol[MTOK*HDIM];
__device__ bf16 g_knh[MTOK*HDIM], g_knl[MTOK*HDIM];
__device__ bf16 g_ah [(size_t)MTOK*SLOTS], g_al[(size_t)MTOK*SLOTS];
__device__ bf16 g_kmh[SLOTS*HDIM], g_kml[SLOTS*HDIM];
__device__ bf16 g_vth[HDIM*SLOTS], g_vtl[HDIM*SLOTS];
__device__ bf16 g_winh[HDIM*HDIM], g_winl[HDIM*HDIM];
__device__ bf16 g_wqh [HDIM*HDIM], g_wql [HDIM*HDIM];
__device__ bf16 g_wkvh[KVW*512],   g_wkvl[KVW*512];
__device__ bf16 g_woh [HDIM*512],  g_wol [HDIM*512];

// ======================= low-level helpers ======================================
__device__ __forceinline__ uint32_t smem_u32(const void* p) {
    uint32_t a;
    asm("{ .reg .u64 t; cvta.to.shared.u64 t, %1; cvt.u32.u64 %0, t; }" : "=r"(a) : "l"(p));
    return a;
}
__device__ __forceinline__ void cp16(uint32_t s, const void* g) {
    asm volatile("cp.async.cg.shared.global [%0], [%1], 16;" :: "r"(s), "l"(g));
}
#define CP_COMMIT() asm volatile("cp.async.commit_group;" ::: "memory")
#define CP_WAIT(n)  asm volatile("cp.async.wait_group %0;" :: "n"(n) : "memory")

#define LDM4(R, A) asm volatile( \
    "ldmatrix.sync.aligned.m8n8.x4.shared.b16 {%0,%1,%2,%3}, [%4];" \
    : "=r"((R)[0]), "=r"((R)[1]), "=r"((R)[2]), "=r"((R)[3]) : "r"(A))

__device__ __forceinline__ void mma16816(float* c, const uint32_t* a, const uint32_t* b) {
    asm volatile(
        "mma.sync.aligned.m16n8k16.row.col.f32.bf16.bf16.f32 "
        "{%0,%1,%2,%3}, {%4,%5,%6,%7}, {%8,%9}, {%0,%1,%2,%3};"
        : "+f"(c[0]), "+f"(c[1]), "+f"(c[2]), "+f"(c[3])
        : "r"(a[0]), "r"(a[1]), "r"(a[2]), "r"(a[3]), "r"(b[0]), "r"(b[1]));
}

// ======================= split-bf16 HMMA GEMM ====================================
// C[M,N] = concat(A0,A1)[M,K] @ B[N,K]^T * scale + bias
// CTA tile 128x128, 8 warps (warp tile 32m x 64n), BK=32, 3-stage cp.async.
#define STG   40960                 // bytes per stage (4 ops x 128 x 40 bf16)
#define GSMEM (3 * STG)             // 122,880 B dynamic smem
#define LDSB  80                    // smem row stride in bytes (40 bf16)

__global__ __launch_bounds__(256, 1)
void gemm_bf16s(const bf16* __restrict__ Ah0, const bf16* __restrict__ Al0, int lda0,
                const bf16* __restrict__ Ah1, const bf16* __restrict__ Al1, int lda1,
                int K0, int K,
                const bf16* __restrict__ Bh, const bf16* __restrict__ Bl,
                const float* __restrict__ bias, float scale,
                float* __restrict__ C, int N)
{
    extern __shared__ __align__(128) char smx[];
    const uint32_t sb = smem_u32(smx);
    const int tid  = threadIdx.x;
    const int lane = tid & 31, wid = tid >> 5;
    const int wm   = wid & 3,  wn  = wid >> 2;
    const long blkm = (long)blockIdx.y * 128;
    const long blkn = (long)blockIdx.x * 128;
    const int NIT = K >> 5;

    // per-thread gmem chunk (two per matrix per stage)
    const int r0 = tid >> 2,            c0 = (tid & 3);
    const int r1 = (tid + 256) >> 2,    c1 = ((tid + 256) & 3);

    float acc[2][8][4];
#pragma unroll
    for (int a = 0; a < 2; a++)
#pragma unroll
        for (int b = 0; b < 8; b++)
#pragma unroll
            for (int d = 0; d < 4; d++) acc[a][b][d] = 0.f;

#define LOAD_STAGE(IT) do {                                                        \
        const int _it = (IT);                                                      \
        const int _k0 = _it << 5;                                                  \
        const bf16 *_ah, *_al; long _lda; long _kc;                                \
        if (_k0 < K0) { _ah = Ah0; _al = Al0; _lda = lda0; _kc = _k0; }            \
        else          { _ah = Ah1; _al = Al1; _lda = lda1; _kc = _k0 - K0; }       \
        const bf16* _ar = _ah + blkm * _lda + _kc;                                 \
        const bf16* _alr= _al + blkm * _lda + _kc;                                 \
        const bf16* _br = Bh + blkn * (long)K + _k0;                               \
        const bf16* _blr= Bl + blkn * (long)K + _k0;                               \
        const uint32_t _bs = sb + (uint32_t)(_it % 3) * STG;                       \
        cp16(_bs +         (uint32_t)(r0*LDSB + c0*16), _ar  + (long)r0*_lda + c0*8); \
        cp16(_bs +         (uint32_t)(r1*LDSB + c1*16), _ar  + (long)r1*_lda + c1*8); \
        cp16(_bs + 10240 + (uint32_t)(r0*LDSB + c0*16), _alr + (long)r0*_lda + c0*8); \
        cp16(_bs + 10240 + (uint32_t)(r1*LDSB + c1*16), _alr + (long)r1*_lda + c1*8); \
        cp16(_bs + 20480 + (uint32_t)(r0*LDSB + c0*16), _br  + (long)r0*K + c0*8);    \
        cp16(_bs + 20480 + (uint32_t)(r1*LDSB + c1*16), _br  + (long)r1*K + c1*8);    \
        cp16(_bs + 30720 + (uint32_t)(r0*LDSB + c0*16), _blr + (long)r0*K + c0*8);    \
        cp16(_bs + 30720 + (uint32_t)(r1*LDSB + c1*16), _blr + (long)r1*K + c1*8);    \
        CP_COMMIT();                                                               \
    } while (0)

    LOAD_STAGE(0);
    if (NIT > 1) LOAD_STAGE(1);

    // ldmatrix base offsets (within a stage)
    const uint32_t a_off = (uint32_t)((wm*32 + (lane & 15)) * LDSB + (lane >> 4) * 16);
    const uint32_t b_off = (uint32_t)((wn*64 + ((lane >> 4) << 3) + (lane & 7)) * LDSB
                                      + ((lane >> 3) & 1) * 16);

    for (int it = 0; it < NIT; it++) {
        if (it + 1 < NIT) CP_WAIT(1); else CP_WAIT(0);
        __syncthreads();
        const uint32_t base = sb + (uint32_t)(it % 3) * STG;
#pragma unroll
        for (int kk = 0; kk < 2; kk++) {
            const uint32_t ka = base + a_off + kk * 32;
            const uint32_t kb = base + b_off + kk * 32;
            uint32_t AH[2][4], AL[2][4], BH[4][4], BL[4][4];
            LDM4(AH[0], ka);
            LDM4(AH[1], ka + 16 * LDSB);
            LDM4(AL[0], ka + 10240);
            LDM4(AL[1], ka + 10240 + 16 * LDSB);
#pragma unroll
            for (int p = 0; p < 4; p++) {
                LDM4(BH[p], kb + 20480 + p * 16 * LDSB);
                LDM4(BL[p], kb + 30720 + p * 16 * LDSB);
            }
#pragma unroll
            for (int mf = 0; mf < 2; mf++)
#pragma unroll
                for (int nf = 0; nf < 8; nf++) {
                    const uint32_t* bh = &BH[nf >> 1][(nf & 1) * 2];
                    const uint32_t* bl = &BL[nf >> 1][(nf & 1) * 2];
                    mma16816(acc[mf][nf], AH[mf], bh);
                    mma16816(acc[mf][nf], AH[mf], bl);
                    mma16816(acc[mf][nf], AL[mf], bh);
                }
        }
        if (it + 2 < NIT) LOAD_STAGE(it + 2);
    }

    // epilogue: lane l of frag (mf,nf): c0,c1 -> (m, n), (m, n+1); c2,c3 -> (m+8, ...)
#pragma unroll
    for (int mf = 0; mf < 2; mf++) {
        const long m0 = blkm + wm * 32 + mf * 16 + (lane >> 2);
#pragma unroll
        for (int nf = 0; nf < 8; nf++) {
            const long n0 = blkn + wn * 64 + nf * 8 + (lane & 3) * 2;
            float b0 = bias ? bias[n0]     : 0.f;
            float b1 = bias ? bias[n0 + 1] : 0.f;
            float2 v0, v1;
            v0.x = acc[mf][nf][0] * scale + b0;
            v0.y = acc[mf][nf][1] * scale + b1;
            v1.x = acc[mf][nf][2] * scale + b0;
            v1.y = acc[mf][nf][3] * scale + b1;
            *(float2*)(C + m0 * (long)N + n0)       = v0;
            *(float2*)(C + (m0 + 8) * (long)N + n0) = v1;
        }
    }
#undef LOAD_STAGE
}

// ======================= split conversions ======================================
__global__ void conv_split(const float* __restrict__ src, long sstride, int Cc, long total,
                           bf16* __restrict__ hi, bf16* __restrict__ lo)
{
    long i = (long)blockIdx.x * 256 + threadIdx.x;
    if (i >= total) return;
    long r = i / Cc; int cc = (int)(i - r * Cc);
    float v = src[r * sstride + cc];
    bf16 h = __float2bfloat16(v);
    hi[i] = h;
    lo[i] = __float2bfloat16(v - __bfloat162float(h));
}

__global__ void conv_split_T(const float* __restrict__ src, int R, int Cc,
                             bf16* __restrict__ hi, bf16* __restrict__ lo)
{
    long i = (long)blockIdx.x * 256 + threadIdx.x;
    if (i >= (long)R * Cc) return;
    int r = (int)(i / Cc), cc = (int)(i - (long)r * Cc);
    float v = src[i];
    bf16 h = __float2bfloat16(v);
    long o = (long)cc * R + r;
    hi[o] = h;
    lo[o] = __float2bfloat16(v - __bfloat162float(h));
}

// ======================= reductions ==============================================
__device__ __forceinline__ float block_sum_256(float v, float* red)
{
#pragma unroll
    for (int o = 16; o > 0; o >>= 1) v += __shfl_xor_sync(0xffffffffu, v, o);
    if ((threadIdx.x & 31) == 0) red[threadIdx.x >> 5] = v;
    __syncthreads();
    float t = 0.f;
#pragma unroll
    for (int i = 0; i < 8; i++) t += red[i];
    __syncthreads();
    return t;
}
__device__ __forceinline__ float block_max_256(float v, float* red)
{
#pragma unroll
    for (int o = 16; o > 0; o >>= 1) v = fmaxf(v, __shfl_xor_sync(0xffffffffu, v, o));
    if ((threadIdx.x & 31) == 0) red[threadIdx.x >> 5] = v;
    __syncthreads();
    float t = -INFINITY;
#pragma unroll
    for (int i = 0; i < 8; i++) t = fmaxf(t, red[i]);
    __syncthreads();
    return t;
}

// ======================= softmax + split of attn ================================
__global__ __launch_bounds__(256)
void softmax_kernel(const float* __restrict__ sim, bf16* __restrict__ ah,
                    bf16* __restrict__ al, float* __restrict__ surp)
{
    __shared__ float red[8];
    const long row = blockIdx.x;
    const int tid = threadIdx.x;
    const float* sr = sim + row * SLOTS;
    float v[16], mloc = -INFINITY;
#pragma unroll
    for (int i = 0; i < 16; i++) { v[i] = sr[tid + (i << 8)]; mloc = fmaxf(mloc, v[i]); }
    float m = block_max_256(mloc, red);
    float s = 0.f;
#pragma unroll
    for (int i = 0; i < 16; i++) s += expf(v[i] - m);
    float Z = block_sum_256(s, red);
    float inv = 1.f / Z;
#pragma unroll
    for (int i = 0; i < 16; i++) {
        float p = expf(v[i] - m) * inv;
        bf16 h = __float2bfloat16(p);
        long o = row * SLOTS + tid + (i << 8);
        ah[o] = h;
        al[o] = __float2bfloat16(p - __bfloat162float(h));
    }
    if (tid == 0) surp[row] = 1.f - inv;
}

// ======================= elementwise / epilogue kernels =========================
__global__ void zero_kernel()
{
    int i = blockIdx.x * blockDim.x + threadIdx.x;
    if (i < SLOTS*HDIM) { g_gk[i] = 0.f; g_gv[i] = 0.f; }
    if (i < SLOTS) g_gcnt[i] = 0.f;
}

__global__ __launch_bounds__(256)
void ln_gelu_kernel(float* __restrict__ X, const float* __restrict__ gm,
                    const float* __restrict__ bt, int W)
{
    __shared__ float red[8];
    const int row = blockIdx.x, tid = threadIdx.x;
    float* xr = X + (size_t)row * W;
    const int cnt = W >> 8;
    float vals[3];
    float s = 0.f;
    for (int i = 0; i < cnt; i++) { vals[i] = xr[tid + (i << 8)]; s += vals[i]; }
    float mean = block_sum_256(s, red) / (float)W;
    float sq = 0.f;
    for (int i = 0; i < cnt; i++) { float d = vals[i] - mean; sq += d * d; }
    float var  = block_sum_256(sq, red) / (float)W;
    float rstd = rsqrtf(var + 1e-5f);
    for (int i = 0; i < cnt; i++) {
        int c = tid + (i << 8);
        float t = (vals[i] - mean) * rstd * gm[c] + bt[c];
        xr[c] = 0.5f * t * (1.f + erff(t * 0.70710678f));
    }
}

__global__ __launch_bounds__(256)
void lr_kernel(const float* __restrict__ KV, float* __restrict__ lr)
{
    __shared__ float red[8];
    const int row = blockIdx.x, tid = threadIdx.x;
    float x = KV[(size_t)row * KVW + 512 + tid];
    float s = 1.f / (1.f + expf(-x));
    float tot = block_sum_256(s, red);
    if (tid == 0) lr[row] = tot * (1.f / 256.f);
}

__global__ void memupd_kernel(const float* __restrict__ Km, const float* __restrict__ Vm,
                              float* __restrict__ Kout, float* __restrict__ Vout)
{
    int i = blockIdx.x * blockDim.x + threadIdx.x;
    float cnt = g_gcnt[i >> 8];
    float k = Km[i], v = Vm[i];
    Kout[i] = k + 0.1f * (g_gk[i] - cnt * k);
    Vout[i] = v + 0.1f * (g_gv[i] - cnt * v);
}

__global__ __launch_bounds__(256)
void final_ln_kernel(const float* __restrict__ opre, const float* __restrict__ xproj,
                     const float* __restrict__ go, const float* __restrict__ beo,
                     const float* __restrict__ g1, const float* __restrict__ be1,
                     float* __restrict__ out)
{
    __shared__ float red[8];
    const int row = blockIdx.x, tid = threadIdx.x;
    float v    = opre[(size_t)row * HDIM + tid];
    float mean = block_sum_256(v, red) * (1.f / 256.f);
    float d    = v - mean;
    float var  = block_sum_256(d * d, red) * (1.f / 256.f);
    float t    = d * rsqrtf(var + 1e-5f) * go[tid] + beo[tid];
    float u    = t + xproj[(size_t)row * HDIM + tid];
    float m2   = block_sum_256(u, red) * (1.f / 256.f);
    float d2   = u - m2;
    float v2   = block_sum_256(d2 * d2, red) * (1.f / 256.f);
    out[(size_t)row * HDIM + tid] = d2 * rsqrtf(v2 + 1e-5f) * g1[tid] + be1[tid];
}

// ======================= exact argmax + gated scatter ===========================
__global__ __launch_bounds__(256)
void argmax_scatter(const float* __restrict__ wsim, const float* __restrict__ kvbuf,
                    const float* __restrict__ Km, const float* __restrict__ surp)
{
    __shared__ float red[8];
    __shared__ int s_cnt;
    __shared__ int s_cand[64];
    const long row = blockIdx.x;
    const int tid = threadIdx.x;
    const float* wr = wsim + row * SLOTS;
    float v[16], mloc = -INFINITY;
#pragma unroll
    for (int i = 0; i < 16; i++) { v[i] = wr[tid + (i << 8)]; mloc = fmaxf(mloc, v[i]); }
    float m = block_max_256(mloc, red);
    if (tid == 0) s_cnt = 0;
    __syncthreads();
#pragma unroll
    for (int i = 0; i < 16; i++) {
        if (v[i] >= m - 1e-2f) {
            int p = atomicAdd(&s_cnt, 1);
            if (p < 64) s_cand[p] = tid + (i << 8);
        }
    }
    __syncthreads();
    int n = s_cnt < 64 ? s_cnt : 64;
    const float kn = kvbuf[row * KVW + tid];   // key_new[row, tid]
    float bestv = -INFINITY; int besti = 0x7fffffff;
    for (int j = 0; j < n; j++) {
        int slot = s_cand[j];
        float s = block_sum_256(kn * Km[(long)slot * HDIM + tid], red);  // exact fp32 rescore
        if (s > bestv || (s == bestv && slot < besti)) { bestv = s; besti = slot; }
    }
    float gate = surp[row];
    atomicAdd(&g_gk[(long)besti * HDIM + tid], gate * kn);
    atomicAdd(&g_gv[(long)besti * HDIM + tid], gate * kvbuf[row * KVW + HDIM + tid]);
    if (tid == 0) atomicAdd(&g_gcnt[besti], gate);
}

// =================================================================================
extern "C" void kernel_launch(void* const* d_in, const int* in_sizes, int n_in,
                              void* d_out, int out_size)
{
    const float* x    = (const float*)d_in[0];
    const float* W_in = (const float*)d_in[1];
    const float* b_in = (const float*)d_in[2];
    const float* W_q  = (const float*)d_in[3];
    const float* b_q  = (const float*)d_in[4];
    const float* gq   = (const float*)d_in[5];
    const float* beq  = (const float*)d_in[6];
    const float* Km   = (const float*)d_in[7];
    const float* Vm   = (const float*)d_in[8];
    const float* W_kv = (const float*)d_in[9];
    const float* b_kv = (const float*)d_in[10];
    const float* gkv  = (const float*)d_in[11];
    const float* bekv = (const float*)d_in[12];
    const float* W_o  = (const float*)d_in[13];
    const float* b_o  = (const float*)d_in[14];
    const float* go   = (const float*)d_in[15];
    const float* beo  = (const float*)d_in[16];
    const float* g1   = (const float*)d_in[17];
    const float* be1  = (const float*)d_in[18];

    float* out    = (float*)d_out;
    float* o_out  = out;
    float* k_out  = out + 8388608;
    float* v_out  = out + 9437184;
    float* s_out  = out + 10485760;
    float* lr_out = out + 10518528;

    float *p_xproj, *p_query, *p_memout, *p_kvbuf, *p_opre, *p_sim;
    cudaGetSymbolAddress((void**)&p_xproj,  g_xproj);
    cudaGetSymbolAddress((void**)&p_query,  g_query);
    cudaGetSymbolAddress((void**)&p_memout, g_memout);
    cudaGetSymbolAddress((void**)&p_kvbuf,  g_kvbuf);
    cudaGetSymbolAddress((void**)&p_opre,   g_opre);
    cudaGetSymbolAddress((void**)&p_sim,    g_sim);
    bf16 *xh,*xl,*xph,*xpl,*qh,*ql,*moh,*mol,*knh,*knl,*ah,*al;
    bf16 *kmh,*kml,*vth,*vtl,*winh,*winl,*wqh,*wql,*wkvh,*wkvl,*woh,*wol;
    cudaGetSymbolAddress((void**)&xh,  g_xh);  cudaGetSymbolAddress((void**)&xl,  g_xl);
    cudaGetSymbolAddress((void**)&xph, g_xph); cudaGetSymbolAddress((void**)&xpl, g_xpl);
    cudaGetSymbolAddress((void**)&qh,  g_qh);  cudaGetSymbolAddress((void**)&ql,  g_ql);
    cudaGetSymbolAddress((void**)&moh, g_moh); cudaGetSymbolAddress((void**)&mol, g_mol);
    cudaGetSymbolAddress((void**)&knh, g_knh); cudaGetSymbolAddress((void**)&knl, g_knl);
    cudaGetSymbolAddress((void**)&ah,  g_ah);  cudaGetSymbolAddress((void**)&al,  g_al);
    cudaGetSymbolAddress((void**)&kmh, g_kmh); cudaGetSymbolAddress((void**)&kml, g_kml);
    cudaGetSymbolAddress((void**)&vth, g_vth); cudaGetSymbolAddress((void**)&vtl, g_vtl);
    cudaGetSymbolAddress((void**)&winh,g_winh);cudaGetSymbolAddress((void**)&winl,g_winl);
    cudaGetSymbolAddress((void**)&wqh, g_wqh); cudaGetSymbolAddress((void**)&wql, g_wql);
    cudaGetSymbolAddress((void**)&wkvh,g_wkvh);cudaGetSymbolAddress((void**)&wkvl,g_wkvl);
    cudaGetSymbolAddress((void**)&woh, g_woh); cudaGetSymbolAddress((void**)&wol, g_wol);

    cudaFuncSetAttribute(gemm_bf16s, cudaFuncAttributeMaxDynamicSharedMemorySize, GSMEM);

    const long NTOKH = (long)MTOK * HDIM;      // 8388608

    zero_kernel<<<4096, 256>>>();

    // weight / memory conversions (B operands are [N][K] row-major)
    conv_split_T<<<(256*256+255)/256, 256>>>(W_in, 256, 256, winh, winl);
    conv_split_T<<<(256*256+255)/256, 256>>>(W_q,  256, 256, wqh,  wql);
    conv_split_T<<<(512*768+255)/256, 256>>>(W_kv, 512, 768, wkvh, wkvl);
    conv_split_T<<<(512*256+255)/256, 256>>>(W_o,  512, 256, woh,  wol);
    conv_split  <<<(SLOTS*HDIM+255)/256, 256>>>(Km, 256, 256, (long)SLOTS*HDIM, kmh, kml);
    conv_split_T<<<(SLOTS*HDIM+255)/256, 256>>>(Vm, SLOTS, 256, vth, vtl);
    conv_split  <<<(NTOKH+255)/256, 256>>>(x, 256, 256, NTOKH, xh, xl);

    // x_proj = x @ W_in + b_in
    gemm_bf16s<<<dim3(2,256), 256, GSMEM>>>(xh, xl, 256, xh, xl, 256, 256, 256,
                                            winh, winl, b_in, 1.f, p_xproj, 256);
    conv_split<<<(NTOKH+255)/256, 256>>>(p_xproj, 256, 256, NTOKH, xph, xpl);

    // query = gelu(LN(x_proj @ W_q + b_q))
    gemm_bf16s<<<dim3(2,256), 256, GSMEM>>>(xph, xpl, 256, xph, xpl, 256, 256, 256,
                                            wqh, wql, b_q, 1.f, p_query, 256);
    ln_gelu_kernel<<<32768, 256>>>(p_query, gq, beq, 256);
    conv_split<<<(NTOKH+255)/256, 256>>>(p_query, 256, 256, NTOKH, qh, ql);

    // sim = query @ K_mem^T / 16
    gemm_bf16s<<<dim3(32,256), 256, GSMEM>>>(qh, ql, 256, qh, ql, 256, 256, 256,
                                             kmh, kml, nullptr, 0.0625f, p_sim, SLOTS);
    softmax_kernel<<<32768, 256>>>(p_sim, ah, al, s_out);

    // mem_out = attn @ V_mem
    gemm_bf16s<<<dim3(2,256), 256, GSMEM>>>(ah, al, SLOTS, ah, al, SLOTS, SLOTS, SLOTS,
                                            vth, vtl, nullptr, 1.f, p_memout, 256);
    conv_split<<<(NTOKH+255)/256, 256>>>(p_memout, 256, 256, NTOKH, moh, mol);

    // kv_lr = gelu(LN(concat(x_proj, mem_out) @ W_kv + b_kv))
    gemm_bf16s<<<dim3(6,256), 256, GSMEM>>>(xph, xpl, 256, moh, mol, 256, 256, 512,
                                            wkvh, wkvl, b_kv, 1.f, p_kvbuf, 768);
    ln_gelu_kernel<<<32768, 256>>>(p_kvbuf, gkv, bekv, 768);
    lr_kernel<<<32768, 256>>>(p_kvbuf, lr_out);
    conv_split<<<(NTOKH+255)/256, 256>>>(p_kvbuf, 768, 256, NTOKH, knh, knl);

    // wsim = key_new @ K_mem^T, then exact argmax + scatter
    gemm_bf16s<<<dim3(32,256), 256, GSMEM>>>(knh, knl, 256, knh, knl, 256, 256, 256,
                                             kmh, kml, nullptr, 1.f, p_sim, SLOTS);
    argmax_scatter<<<32768, 256>>>(p_sim, p_kvbuf, Km, s_out);
    memupd_kernel<<<4096, 256>>>(Km, Vm, k_out, v_out);

    // out = LN(LN(combined @ W_o + b_o) + x_proj)
    gemm_bf16s<<<dim3(2,256), 256, GSMEM>>>(xph, xpl, 256, moh, mol, 256, 256, 512,
                                            woh, wol, b_o, 1.f, p_opre, 256);
    final_ln_kernel<<<32768, 256>>>(p_opre, p_xproj, go, beo, g1, be1, o_out);
}

// round 5
// speedup vs baseline: 5.4901x; 1.2417x over previous
#include <cuda_runtime.h>
#include <cuda_bf16.h>
#include <math.h>
#include <stdint.h>

#define MTOK  32768
#define HDIM  256
#define SLOTS 4096
#define KVW   768

typedef __nv_bfloat16 bf16;

// ======================= static scratch (no allocation) ========================
__device__ float g_xproj [MTOK*HDIM];
__device__ float g_query [MTOK*HDIM];
__device__ float g_memout[MTOK*HDIM];
__device__ float g_kvbuf [MTOK*KVW];
__device__ float g_opre  [MTOK*HDIM];
__device__ float g_sim   [(size_t)MTOK*SLOTS];     // sim, then reused for wsim
__device__ float g_gk    [SLOTS*HDIM];
__device__ float g_gv    [SLOTS*HDIM];
__device__ float g_gcnt  [SLOTS];

__device__ bf16 g_xh [MTOK*HDIM], g_xl [MTOK*HDIM];
__device__ bf16 g_xph[MTOK*HDIM], g_xpl[MTOK*HDIM];
__device__ bf16 g_qh [MTOK*HDIM];
__device__ bf16 g_moh[MTOK*HDIM], g_mol[MTOK*HDIM];
__device__ bf16 g_knh[MTOK*HDIM];
__device__ bf16 g_ah [(size_t)MTOK*SLOTS], g_al[(size_t)MTOK*SLOTS];
__device__ bf16 g_kmh[SLOTS*HDIM], g_kml[SLOTS*HDIM];
__device__ bf16 g_vth[HDIM*SLOTS], g_vtl[HDIM*SLOTS];
__device__ bf16 g_winh[HDIM*HDIM], g_winl[HDIM*HDIM];
__device__ bf16 g_wqh [HDIM*HDIM], g_wql [HDIM*HDIM];
__device__ bf16 g_wkvh[KVW*512],   g_wkvl[KVW*512];
__device__ bf16 g_woh [HDIM*512],  g_wol [HDIM*512];

// ======================= low-level helpers ======================================
__device__ __forceinline__ uint32_t smem_u32(const void* p) {
    uint32_t a;
    asm("{ .reg .u64 t; cvta.to.shared.u64 t, %1; cvt.u32.u64 %0, t; }" : "=r"(a) : "l"(p));
    return a;
}
__device__ __forceinline__ void cp16(uint32_t s, const void* g) {
    asm volatile("cp.async.cg.shared.global [%0], [%1], 16;" :: "r"(s), "l"(g));
}
#define CP_COMMIT() asm volatile("cp.async.commit_group;" ::: "memory")
#define CP_WAIT(n)  asm volatile("cp.async.wait_group %0;" :: "n"(n) : "memory")

#define LDM4(R, A) asm volatile( \
    "ldmatrix.sync.aligned.m8n8.x4.shared.b16 {%0,%1,%2,%3}, [%4];" \
    : "=r"((R)[0]), "=r"((R)[1]), "=r"((R)[2]), "=r"((R)[3]) : "r"(A))

__device__ __forceinline__ void mma16816(float* c, const uint32_t* a, const uint32_t* b) {
    asm volatile(
        "mma.sync.aligned.m16n8k16.row.col.f32.bf16.bf16.f32 "
        "{%0,%1,%2,%3}, {%4,%5,%6,%7}, {%8,%9}, {%0,%1,%2,%3};"
        : "+f"(c[0]), "+f"(c[1]), "+f"(c[2]), "+f"(c[3])
        : "r"(a[0]), "r"(a[1]), "r"(a[2]), "r"(a[3]), "r"(b[0]), "r"(b[1]));
}

// ======================= split-bf16 HMMA GEMM ====================================
// C[M,N] = concat(A0,A1)[M,K] @ B[N,K]^T * scale + bias
// NS = number of split MMAs: 3 (hh+hl+lh), 2 (hh+hl), 1 (hh).
// CTA tile 128x128, 8 warps (warp tile 32m x 64n), BK=32, 3-stage cp.async.
#define STG   40960                 // bytes per stage (4 ops x 128 x 40 bf16)
#define GSMEM (3 * STG)             // 122,880 B dynamic smem
#define LDSB  80                    // smem row stride in bytes (40 bf16)

template<int NS>
__global__ __launch_bounds__(256, 1)
void gemm_bf16s(const bf16* __restrict__ Ah0, const bf16* __restrict__ Al0, int lda0,
                const bf16* __restrict__ Ah1, const bf16* __restrict__ Al1, int lda1,
                int K0, int K,
                const bf16* __restrict__ Bh, const bf16* __restrict__ Bl,
                const float* __restrict__ bias, float scale,
                float* __restrict__ C, int N,
                bf16* __restrict__ HiO, bf16* __restrict__ LoO)
{
    extern __shared__ __align__(128) char smx[];
    const uint32_t sb = smem_u32(smx);
    const int tid  = threadIdx.x;
    const int lane = tid & 31, wid = tid >> 5;
    const int wm   = wid & 3,  wn  = wid >> 2;
    const long blkm = (long)blockIdx.y * 128;
    const long blkn = (long)blockIdx.x * 128;
    const int NIT = K >> 5;

    const int r0 = tid >> 2,            c0 = (tid & 3);
    const int r1 = (tid + 256) >> 2,    c1 = ((tid + 256) & 3);

    float acc[2][8][4];
#pragma unroll
    for (int a = 0; a < 2; a++)
#pragma unroll
        for (int b = 0; b < 8; b++)
#pragma unroll
            for (int d = 0; d < 4; d++) acc[a][b][d] = 0.f;

#define LOAD_STAGE(IT) do {                                                        \
        const int _it = (IT);                                                      \
        const int _k0 = _it << 5;                                                  \
        const bf16 *_ah, *_al; long _lda; long _kc;                                \
        if (_k0 < K0) { _ah = Ah0; _al = Al0; _lda = lda0; _kc = _k0; }            \
        else          { _ah = Ah1; _al = Al1; _lda = lda1; _kc = _k0 - K0; }       \
        const bf16* _ar = _ah + blkm * _lda + _kc;                                 \
        const bf16* _br = Bh + blkn * (long)K + _k0;                               \
        const uint32_t _bs = sb + (uint32_t)(_it % 3) * STG;                       \
        cp16(_bs +         (uint32_t)(r0*LDSB + c0*16), _ar  + (long)r0*_lda + c0*8); \
        cp16(_bs +         (uint32_t)(r1*LDSB + c1*16), _ar  + (long)r1*_lda + c1*8); \
        if (NS == 3) {                                                             \
            const bf16* _alr = _al + blkm * _lda + _kc;                            \
            cp16(_bs + 10240 + (uint32_t)(r0*LDSB + c0*16), _alr + (long)r0*_lda + c0*8); \
            cp16(_bs + 10240 + (uint32_t)(r1*LDSB + c1*16), _alr + (long)r1*_lda + c1*8); \
        }                                                                          \
        cp16(_bs + 20480 + (uint32_t)(r0*LDSB + c0*16), _br  + (long)r0*K + c0*8);    \
        cp16(_bs + 20480 + (uint32_t)(r1*LDSB + c1*16), _br  + (long)r1*K + c1*8);    \
        if (NS >= 2) {                                                             \
            const bf16* _blr = Bl + blkn * (long)K + _k0;                          \
            cp16(_bs + 30720 + (uint32_t)(r0*LDSB + c0*16), _blr + (long)r0*K + c0*8);    \
            cp16(_bs + 30720 + (uint32_t)(r1*LDSB + c1*16), _blr + (long)r1*K + c1*8);    \
        }                                                                          \
        CP_COMMIT();                                                               \
    } while (0)

    LOAD_STAGE(0);
    if (NIT > 1) LOAD_STAGE(1);

    const uint32_t a_off = (uint32_t)((wm*32 + (lane & 15)) * LDSB + (lane >> 4) * 16);
    const uint32_t b_off = (uint32_t)((wn*64 + ((lane >> 4) << 3) + (lane & 7)) * LDSB
                                      + ((lane >> 3) & 1) * 16);

    for (int it = 0; it < NIT; it++) {
        if (it + 1 < NIT) CP_WAIT(1); else CP_WAIT(0);
        __syncthreads();
        const uint32_t base = sb + (uint32_t)(it % 3) * STG;
#pragma unroll
        for (int kk = 0; kk < 2; kk++) {
            const uint32_t ka = base + a_off + kk * 32;
            const uint32_t kb = base + b_off + kk * 32;
            uint32_t AH[2][4], AL[2][4], BH[4][4], BL[4][4];
            LDM4(AH[0], ka);
            LDM4(AH[1], ka + 16 * LDSB);
            if (NS == 3) {
                LDM4(AL[0], ka + 10240);
                LDM4(AL[1], ka + 10240 + 16 * LDSB);
            }
#pragma unroll
            for (int p = 0; p < 4; p++) {
                LDM4(BH[p], kb + 20480 + p * 16 * LDSB);
                if (NS >= 2) LDM4(BL[p], kb + 30720 + p * 16 * LDSB);
            }
#pragma unroll
            for (int mf = 0; mf < 2; mf++)
#pragma unroll
                for (int nf = 0; nf < 8; nf++) {
                    const uint32_t* bh = &BH[nf >> 1][(nf & 1) * 2];
                    mma16816(acc[mf][nf], AH[mf], bh);
                    if (NS >= 2) {
                        const uint32_t* bl = &BL[nf >> 1][(nf & 1) * 2];
                        mma16816(acc[mf][nf], AH[mf], bl);
                    }
                    if (NS == 3) mma16816(acc[mf][nf], AL[mf], bh);
                }
        }
        if (it + 2 < NIT) LOAD_STAGE(it + 2);
    }

#pragma unroll
    for (int mf = 0; mf < 2; mf++) {
        const long m0 = blkm + wm * 32 + mf * 16 + (lane >> 2);
#pragma unroll
        for (int nf = 0; nf < 8; nf++) {
            const long n0 = blkn + wn * 64 + nf * 8 + (lane & 3) * 2;
            float b0 = bias ? bias[n0]     : 0.f;
            float b1 = bias ? bias[n0 + 1] : 0.f;
            float2 v0, v1;
            v0.x = acc[mf][nf][0] * scale + b0;
            v0.y = acc[mf][nf][1] * scale + b1;
            v1.x = acc[mf][nf][2] * scale + b0;
            v1.y = acc[mf][nf][3] * scale + b1;
            *(float2*)(C + m0 * (long)N + n0)       = v0;
            *(float2*)(C + (m0 + 8) * (long)N + n0) = v1;
            if (HiO) {
                __nv_bfloat162 h0, h1, l0, l1;
                h0.x = __float2bfloat16(v0.x); h0.y = __float2bfloat16(v0.y);
                h1.x = __float2bfloat16(v1.x); h1.y = __float2bfloat16(v1.y);
                l0.x = __float2bfloat16(v0.x - __bfloat162float(h0.x));
                l0.y = __float2bfloat16(v0.y - __bfloat162float(h0.y));
                l1.x = __float2bfloat16(v1.x - __bfloat162float(h1.x));
                l1.y = __float2bfloat16(v1.y - __bfloat162float(h1.y));
                *(__nv_bfloat162*)(HiO + m0 * (long)N + n0)       = h0;
                *(__nv_bfloat162*)(HiO + (m0 + 8) * (long)N + n0) = h1;
                *(__nv_bfloat162*)(LoO + m0 * (long)N + n0)       = l0;
                *(__nv_bfloat162*)(LoO + (m0 + 8) * (long)N + n0) = l1;
            }
        }
    }
#undef LOAD_STAGE
}

// ======================= split conversions ======================================
__global__ void conv_split(const float* __restrict__ src, long sstride, int Cc, long total,
                           bf16* __restrict__ hi, bf16* __restrict__ lo)
{
    long i = (long)blockIdx.x * 256 + threadIdx.x;
    if (i >= total) return;
    long r = i / Cc; int cc = (int)(i - r * Cc);
    float v = src[r * sstride + cc];
    bf16 h = __float2bfloat16(v);
    hi[i] = h;
    lo[i] = __float2bfloat16(v - __bfloat162float(h));
}

__global__ void conv_split_T(const float* __restrict__ src, int R, int Cc,
                             bf16* __restrict__ hi, bf16* __restrict__ lo)
{
    long i = (long)blockIdx.x * 256 + threadIdx.x;
    if (i >= (long)R * Cc) return;
    int r = (int)(i / Cc), cc = (int)(i - (long)r * Cc);
    float v = src[i];
    bf16 h = __float2bfloat16(v);
    long o = (long)cc * R + r;
    hi[o] = h;
    lo[o] = __float2bfloat16(v - __bfloat162float(h));
}

// ======================= reductions ==============================================
__device__ __forceinline__ float block_sum_256(float v, float* red)
{
#pragma unroll
    for (int o = 16; o > 0; o >>= 1) v += __shfl_xor_sync(0xffffffffu, v, o);
    if ((threadIdx.x & 31) == 0) red[threadIdx.x >> 5] = v;
    __syncthreads();
    float t = 0.f;
#pragma unroll
    for (int i = 0; i < 8; i++) t += red[i];
    __syncthreads();
    return t;
}
__device__ __forceinline__ float block_max_256(float v, float* red)
{
#pragma unroll
    for (int o = 16; o > 0; o >>= 1) v = fmaxf(v, __shfl_xor_sync(0xffffffffu, v, o));
    if ((threadIdx.x & 31) == 0) red[threadIdx.x >> 5] = v;
    __syncthreads();
    float t = -INFINITY;
#pragma unroll
    for (int i = 0; i < 8; i++) t = fmaxf(t, red[i]);
    __syncthreads();
    return t;
}

// ======================= softmax + split of attn ================================
__global__ __launch_bounds__(256)
void softmax_kernel(const float* __restrict__ sim, bf16* __restrict__ ah,
                    bf16* __restrict__ al, float* __restrict__ surp)
{
    __shared__ float red[8];
    const long row = blockIdx.x;
    const int tid = threadIdx.x;
    const float* sr = sim + row * SLOTS;
    float v[16], mloc = -INFINITY;
#pragma unroll
    for (int i = 0; i < 16; i++) { v[i] = sr[tid + (i << 8)]; mloc = fmaxf(mloc, v[i]); }
    float m = block_max_256(mloc, red);
    float s = 0.f;
#pragma unroll
    for (int i = 0; i < 16; i++) s += expf(v[i] - m);
    float Z = block_sum_256(s, red);
    float inv = 1.f / Z;
#pragma unroll
    for (int i = 0; i < 16; i++) {
        float p = expf(v[i] - m) * inv;
        bf16 h = __float2bfloat16(p);
        long o = row * SLOTS + tid + (i << 8);
        ah[o] = h;
        al[o] = __float2bfloat16(p - __bfloat162float(h));
    }
    if (tid == 0) surp[row] = 1.f - inv;
}

// ======================= fused LN+GELU variants =================================
__global__ void zero_kernel()
{
    int i = blockIdx.x * blockDim.x + threadIdx.x;
    if (i < SLOTS*HDIM) { g_gk[i] = 0.f; g_gv[i] = 0.f; }
    if (i < SLOTS) g_gcnt[i] = 0.f;
}

// query path: q = gelu(LN(X)); write bf16 hi only
__global__ __launch_bounds__(256)
void ln_gelu_q(const float* __restrict__ X, const float* __restrict__ gm,
               const float* __restrict__ bt, bf16* __restrict__ hi)
{
    __shared__ float red[8];
    const long row = blockIdx.x; const int tid = threadIdx.x;
    float v    = X[row * HDIM + tid];
    float mean = block_sum_256(v, red) * (1.f / 256.f);
    float d    = v - mean;
    float var  = block_sum_256(d * d, red) * (1.f / 256.f);
    float t    = d * rsqrtf(var + 1e-5f) * gm[tid] + bt[tid];
    float g    = 0.5f * t * (1.f + erff(t * 0.70710678f));
    hi[row * HDIM + tid] = __float2bfloat16(g);
}

// kv path: in-place LN+GELU over 768 cols; emit knh (cols 0..255 hi) and lr
__global__ __launch_bounds__(256)
void ln_gelu_kv(float* __restrict__ X, const float* __restrict__ gm,
                const float* __restrict__ bt, bf16* __restrict__ knh,
                float* __restrict__ lr)
{
    __shared__ float red[8];
    const long row = blockIdx.x; const int tid = threadIdx.x;
    float* xr = X + row * KVW;
    float vals[3];
    float s = 0.f;
#pragma unroll
    for (int i = 0; i < 3; i++) { vals[i] = xr[tid + (i << 8)]; s += vals[i]; }
    float mean = block_sum_256(s, red) * (1.f / 768.f);
    float sq = 0.f;
#pragma unroll
    for (int i = 0; i < 3; i++) { float d = vals[i] - mean; sq += d * d; }
    float var  = block_sum_256(sq, red) * (1.f / 768.f);
    float rstd = rsqrtf(var + 1e-5f);
    float gout[3];
#pragma unroll
    for (int i = 0; i < 3; i++) {
        int c = tid + (i << 8);
        float t = (vals[i] - mean) * rstd * gm[c] + bt[c];
        gout[i] = 0.5f * t * (1.f + erff(t * 0.70710678f));
        xr[c] = gout[i];
    }
    knh[row * HDIM + tid] = __float2bfloat16(gout[0]);
    float sg = 1.f / (1.f + expf(-gout[2]));
    float tot = block_sum_256(sg, red);
    if (tid == 0) lr[row] = tot * (1.f / 256.f);
}

__global__ void memupd_kernel(const float* __restrict__ Km, const float* __restrict__ Vm,
                              float* __restrict__ Kout, float* __restrict__ Vout)
{
    int i = blockIdx.x * blockDim.x + threadIdx.x;
    float cnt = g_gcnt[i >> 8];
    float k = Km[i], v = Vm[i];
    Kout[i] = k + 0.1f * (g_gk[i] - cnt * k);
    Vout[i] = v + 0.1f * (g_gv[i] - cnt * v);
}

__global__ __launch_bounds__(256)
void final_ln_kernel(const float* __restrict__ opre, const float* __restrict__ xproj,
                     const float* __restrict__ go, const float* __restrict__ beo,
                     const float* __restrict__ g1, const float* __restrict__ be1,
                     float* __restrict__ out)
{
    __shared__ float red[8];
    const int row = blockIdx.x, tid = threadIdx.x;
    float v    = opre[(size_t)row * HDIM + tid];
    float mean = block_sum_256(v, red) * (1.f / 256.f);
    float d    = v - mean;
    float var  = block_sum_256(d * d, red) * (1.f / 256.f);
    float t    = d * rsqrtf(var + 1e-5f) * go[tid] + beo[tid];
    float u    = t + xproj[(size_t)row * HDIM + tid];
    float m2   = block_sum_256(u, red) * (1.f / 256.f);
    float d2   = u - m2;
    float v2   = block_sum_256(d2 * d2, red) * (1.f / 256.f);
    out[(size_t)row * HDIM + tid] = d2 * rsqrtf(v2 + 1e-5f) * g1[tid] + be1[tid];
}

// ======================= exact argmax + gated scatter ===========================
__global__ __launch_bounds__(256)
void argmax_scatter(const float* __restrict__ wsim, const float* __restrict__ kvbuf,
                    const float* __restrict__ Km, const float* __restrict__ surp)
{
    __shared__ float red[8];
    __shared__ int s_cnt;
    __shared__ int s_cand[128];
    const long row = blockIdx.x;
    const int tid = threadIdx.x;
    const float* wr = wsim + row * SLOTS;
    float v[16], mloc = -INFINITY;
#pragma unroll
    for (int i = 0; i < 16; i++) { v[i] = wr[tid + (i << 8)]; mloc = fmaxf(mloc, v[i]); }
    float m = block_max_256(mloc, red);
    if (tid == 0) s_cnt = 0;
    __syncthreads();
#pragma unroll
    for (int i = 0; i < 16; i++) {
        if (v[i] >= m - 5e-2f) {                 // wider window: single-bf16 wsim
            int p = atomicAdd(&s_cnt, 1);
            if (p < 128) s_cand[p] = tid + (i << 8);
        }
    }
    __syncthreads();
    int n = s_cnt < 128 ? s_cnt : 128;
    const float kn = kvbuf[row * KVW + tid];   // key_new[row, tid]
    float bestv = -INFINITY; int besti = 0x7fffffff;
    for (int j = 0; j < n; j++) {
        int slot = s_cand[j];
        float s = block_sum_256(kn * Km[(long)slot * HDIM + tid], red);  // exact fp32 rescore
        if (s > bestv || (s == bestv && slot < besti)) { bestv = s; besti = slot; }
    }
    float gate = surp[row];
    atomicAdd(&g_gk[(long)besti * HDIM + tid], gate * kn);
    atomicAdd(&g_gv[(long)besti * HDIM + tid], gate * kvbuf[row * KVW + HDIM + tid]);
    if (tid == 0) atomicAdd(&g_gcnt[besti], gate);
}

// =================================================================================
extern "C" void kernel_launch(void* const* d_in, const int* in_sizes, int n_in,
                              void* d_out, int out_size)
{
    const float* x    = (const float*)d_in[0];
    const float* W_in = (const float*)d_in[1];
    const float* b_in = (const float*)d_in[2];
    const float* W_q  = (const float*)d_in[3];
    const float* b_q  = (const float*)d_in[4];
    const float* gq   = (const float*)d_in[5];
    const float* beq  = (const float*)d_in[6];
    const float* Km   = (const float*)d_in[7];
    const float* Vm   = (const float*)d_in[8];
    const float* W_kv = (const float*)d_in[9];
    const float* b_kv = (const float*)d_in[10];
    const float* gkv  = (const float*)d_in[11];
    const float* bekv = (const float*)d_in[12];
    const float* W_o  = (const float*)d_in[13];
    const float* b_o  = (const float*)d_in[14];
    const float* go   = (const float*)d_in[15];
    const float* beo  = (const float*)d_in[16];
    const float* g1   = (const float*)d_in[17];
    const float* be1  = (const float*)d_in[18];

    float* out    = (float*)d_out;
    float* o_out  = out;
    float* k_out  = out + 8388608;
    float* v_out  = out + 9437184;
    float* s_out  = out + 10485760;
    float* lr_out = out + 10518528;

    float *p_xproj, *p_query, *p_memout, *p_kvbuf, *p_opre, *p_sim;
    cudaGetSymbolAddress((void**)&p_xproj,  g_xproj);
    cudaGetSymbolAddress((void**)&p_query,  g_query);
    cudaGetSymbolAddress((void**)&p_memout, g_memout);
    cudaGetSymbolAddress((void**)&p_kvbuf,  g_kvbuf);
    cudaGetSymbolAddress((void**)&p_opre,   g_opre);
    cudaGetSymbolAddress((void**)&p_sim,    g_sim);
    bf16 *xh,*xl,*xph,*xpl,*qh,*moh,*mol,*knh,*ah,*al;
    bf16 *kmh,*kml,*vth,*vtl,*winh,*winl,*wqh,*wql,*wkvh,*wkvl,*woh,*wol;
    cudaGetSymbolAddress((void**)&xh,  g_xh);  cudaGetSymbolAddress((void**)&xl,  g_xl);
    cudaGetSymbolAddress((void**)&xph, g_xph); cudaGetSymbolAddress((void**)&xpl, g_xpl);
    cudaGetSymbolAddress((void**)&qh,  g_qh);
    cudaGetSymbolAddress((void**)&moh, g_moh); cudaGetSymbolAddress((void**)&mol, g_mol);
    cudaGetSymbolAddress((void**)&knh, g_knh);
    cudaGetSymbolAddress((void**)&ah,  g_ah);  cudaGetSymbolAddress((void**)&al,  g_al);
    cudaGetSymbolAddress((void**)&kmh, g_kmh); cudaGetSymbolAddress((void**)&kml, g_kml);
    cudaGetSymbolAddress((void**)&vth, g_vth); cudaGetSymbolAddress((void**)&vtl, g_vtl);
    cudaGetSymbolAddress((void**)&winh,g_winh);cudaGetSymbolAddress((void**)&winl,g_winl);
    cudaGetSymbolAddress((void**)&wqh, g_wqh); cudaGetSymbolAddress((void**)&wql, g_wql);
    cudaGetSymbolAddress((void**)&wkvh,g_wkvh);cudaGetSymbolAddress((void**)&wkvl,g_wkvl);
    cudaGetSymbolAddress((void**)&woh, g_woh); cudaGetSymbolAddress((void**)&wol, g_wol);

    cudaFuncSetAttribute(gemm_bf16s<3>, cudaFuncAttributeMaxDynamicSharedMemorySize, GSMEM);
    cudaFuncSetAttribute(gemm_bf16s<2>, cudaFuncAttributeMaxDynamicSharedMemorySize, GSMEM);
    cudaFuncSetAttribute(gemm_bf16s<1>, cudaFuncAttributeMaxDynamicSharedMemorySize, GSMEM);

    const long NTOKH = (long)MTOK * HDIM;      // 8388608

    zero_kernel<<<4096, 256>>>();

    // weight / memory conversions (B operands are [N][K] row-major)
    conv_split_T<<<(256*256+255)/256, 256>>>(W_in, 256, 256, winh, winl);
    conv_split_T<<<(256*256+255)/256, 256>>>(W_q,  256, 256, wqh,  wql);
    conv_split_T<<<(512*768+255)/256, 256>>>(W_kv, 512, 768, wkvh, wkvl);
    conv_split_T<<<(512*256+255)/256, 256>>>(W_o,  512, 256, woh,  wol);
    conv_split  <<<(SLOTS*HDIM+255)/256, 256>>>(Km, 256, 256, (long)SLOTS*HDIM, kmh, kml);
    conv_split_T<<<(SLOTS*HDIM+255)/256, 256>>>(Vm, SLOTS, 256, vth, vtl);
    conv_split  <<<(NTOKH+255)/256, 256>>>(x, 256, 256, NTOKH, xh, xl);

    // x_proj = x @ W_in + b_in  (fused split out)
    gemm_bf16s<3><<<dim3(2,256), 256, GSMEM>>>(xh, xl, 256, xh, xl, 256, 256, 256,
                                               winh, winl, b_in, 1.f, p_xproj, 256, xph, xpl);

    // query = gelu(LN(x_proj @ W_q + b_q))  -> qh (hi only)
    gemm_bf16s<3><<<dim3(2,256), 256, GSMEM>>>(xph, xpl, 256, xph, xpl, 256, 256, 256,
                                               wqh, wql, b_q, 1.f, p_query, 256, nullptr, nullptr);
    ln_gelu_q<<<32768, 256>>>(p_query, gq, beq, qh);

    // sim = query @ K_mem^T / 16   (NS=2: q hi, K hi+lo)
    gemm_bf16s<2><<<dim3(32,256), 256, GSMEM>>>(qh, nullptr, 256, qh, nullptr, 256, 256, 256,
                                                kmh, kml, nullptr, 0.0625f, p_sim, SLOTS, nullptr, nullptr);
    softmax_kernel<<<32768, 256>>>(p_sim, ah, al, s_out);

    // mem_out = attn @ V_mem  (fused split out)
    gemm_bf16s<3><<<dim3(2,256), 256, GSMEM>>>(ah, al, SLOTS, ah, al, SLOTS, SLOTS, SLOTS,
                                               vth, vtl, nullptr, 1.f, p_memout, 256, moh, mol);

    // kv_lr = gelu(LN(concat(x_proj, mem_out) @ W_kv + b_kv)) ; knh + lr fused
    gemm_bf16s<3><<<dim3(6,256), 256, GSMEM>>>(xph, xpl, 256, moh, mol, 256, 256, 512,
                                               wkvh, wkvl, b_kv, 1.f, p_kvbuf, 768, nullptr, nullptr);
    ln_gelu_kv<<<32768, 256>>>(p_kvbuf, gkv, bekv, knh, lr_out);

    // wsim = key_new @ K_mem^T  (NS=1), then exact argmax + scatter
    gemm_bf16s<1><<<dim3(32,256), 256, GSMEM>>>(knh, nullptr, 256, knh, nullptr, 256, 256, 256,
                                                kmh, nullptr, nullptr, 1.f, p_sim, SLOTS, nullptr, nullptr);
    argmax_scatter<<<32768, 256>>>(p_sim, p_kvbuf, Km, s_out);
    memupd_kernel<<<4096, 256>>>(Km, Vm, k_out, v_out);

    // out = LN(LN(combined @ W_o + b_o) + x_proj)
    gemm_bf16s<3><<<dim3(2,256), 256, GSMEM>>>(xph, xpl, 256, moh, mol, 256, 256, 512,
                                               woh, wol, b_o, 1.f, p_opre, 256, nullptr, nullptr);
    final_ln_kernel<<<32768, 256>>>(p_opre, p_xproj, go, beo, g1, be1, o_out);
}

// round 6
// speedup vs baseline: 6.0730x; 1.1062x over previous
#include <cuda_runtime.h>
#include <cuda_bf16.h>
#include <math.h>
#include <stdint.h>

#define MTOK  32768
#define HDIM  256
#define SLOTS 4096
#define KVW   768

typedef __nv_bfloat16 bf16;

// ======================= static scratch (no allocation) ========================
__device__ float g_xproj [MTOK*HDIM];
__device__ float g_query [MTOK*HDIM];
__device__ float g_memout[MTOK*HDIM];
__device__ float g_kvbuf [MTOK*KVW];
__device__ float g_opre  [MTOK*HDIM];
__device__ float g_gk    [SLOTS*HDIM];
__device__ float g_gv    [SLOTS*HDIM];
__device__ float g_gcnt  [SLOTS];

__device__ bf16 g_wsb[(size_t)MTOK*SLOTS];          // wsim in bf16
__device__ bf16 g_xh [MTOK*HDIM], g_xl [MTOK*HDIM];
__device__ bf16 g_xph[MTOK*HDIM], g_xpl[MTOK*HDIM];
__device__ bf16 g_qh [MTOK*HDIM];
__device__ bf16 g_moh[MTOK*HDIM], g_mol[MTOK*HDIM];
__device__ bf16 g_knh[MTOK*HDIM];
__device__ bf16 g_kmh[SLOTS*HDIM], g_kml[SLOTS*HDIM];
__device__ bf16 g_vth[HDIM*SLOTS], g_vtl[HDIM*SLOTS];
__device__ bf16 g_winh[HDIM*HDIM], g_winl[HDIM*HDIM];
__device__ bf16 g_wqh [HDIM*HDIM], g_wql [HDIM*HDIM];
__device__ bf16 g_wkvh[KVW*512],   g_wkvl[KVW*512];
__device__ bf16 g_woh [HDIM*512],  g_wol [HDIM*512];

// ======================= low-level helpers ======================================
__device__ __forceinline__ uint32_t smem_u32(const void* p) {
    uint32_t a;
    asm("{ .reg .u64 t; cvta.to.shared.u64 t, %1; cvt.u32.u64 %0, t; }" : "=r"(a) : "l"(p));
    return a;
}
__device__ __forceinline__ void cp16(uint32_t s, const void* g) {
    asm volatile("cp.async.cg.shared.global [%0], [%1], 16;" :: "r"(s), "l"(g));
}
#define CP_COMMIT() asm volatile("cp.async.commit_group;" ::: "memory")
#define CP_WAIT(n)  asm volatile("cp.async.wait_group %0;" :: "n"(n) : "memory")

#define LDM4(R, A) asm volatile( \
    "ldmatrix.sync.aligned.m8n8.x4.shared.b16 {%0,%1,%2,%3}, [%4];" \
    : "=r"((R)[0]), "=r"((R)[1]), "=r"((R)[2]), "=r"((R)[3]) : "r"(A))

__device__ __forceinline__ void mma16816(float* c, const uint32_t* a, const uint32_t* b) {
    asm volatile(
        "mma.sync.aligned.m16n8k16.row.col.f32.bf16.bf16.f32 "
        "{%0,%1,%2,%3}, {%4,%5,%6,%7}, {%8,%9}, {%0,%1,%2,%3};"
        : "+f"(c[0]), "+f"(c[1]), "+f"(c[2]), "+f"(c[3])
        : "r"(a[0]), "r"(a[1]), "r"(a[2]), "r"(a[3]), "r"(b[0]), "r"(b[1]));
}
__device__ __forceinline__ uint32_t packbf(float a, float b) {
    __nv_bfloat162 t;
    t.x = __float2bfloat16(a); t.y = __float2bfloat16(b);
    return *(uint32_t*)&t;
}

// ======================= split-bf16 HMMA GEMM ====================================
// C[M,N] = concat(A0,A1)[M,K] @ B[N,K]^T * scale + bias
// NS = number of split MMAs: 3 (hh+hl+lh), 2 (hh+hl), 1 (hh).
#define STG   40960
#define GSMEM (3 * STG)
#define LDSB  80

template<int NS>
__global__ __launch_bounds__(256, 1)
void gemm_bf16s(const bf16* __restrict__ Ah0, const bf16* __restrict__ Al0, int lda0,
                const bf16* __restrict__ Ah1, const bf16* __restrict__ Al1, int lda1,
                int K0, int K,
                const bf16* __restrict__ Bh, const bf16* __restrict__ Bl,
                const float* __restrict__ bias, float scale,
                float* __restrict__ C, int N,
                bf16* __restrict__ HiO, bf16* __restrict__ LoO,
                bf16* __restrict__ Cb)
{
    extern __shared__ __align__(128) char smx[];
    const uint32_t sb = smem_u32(smx);
    const int tid  = threadIdx.x;
    const int lane = tid & 31, wid = tid >> 5;
    const int wm   = wid & 3,  wn  = wid >> 2;
    const long blkm = (long)blockIdx.y * 128;
    const long blkn = (long)blockIdx.x * 128;
    const int NIT = K >> 5;

    const int r0 = tid >> 2,            c0 = (tid & 3);
    const int r1 = (tid + 256) >> 2,    c1 = ((tid + 256) & 3);

    float acc[2][8][4];
#pragma unroll
    for (int a = 0; a < 2; a++)
#pragma unroll
        for (int b = 0; b < 8; b++)
#pragma unroll
            for (int d = 0; d < 4; d++) acc[a][b][d] = 0.f;

#define LOAD_STAGE(IT) do {                                                        \
        const int _it = (IT);                                                      \
        const int _k0 = _it << 5;                                                  \
        const bf16 *_ah, *_al; long _lda; long _kc;                                \
        if (_k0 < K0) { _ah = Ah0; _al = Al0; _lda = lda0; _kc = _k0; }            \
        else          { _ah = Ah1; _al = Al1; _lda = lda1; _kc = _k0 - K0; }       \
        const bf16* _ar = _ah + blkm * _lda + _kc;                                 \
        const bf16* _br = Bh + blkn * (long)K + _k0;                               \
        const uint32_t _bs = sb + (uint32_t)(_it % 3) * STG;                       \
        cp16(_bs +         (uint32_t)(r0*LDSB + c0*16), _ar  + (long)r0*_lda + c0*8); \
        cp16(_bs +         (uint32_t)(r1*LDSB + c1*16), _ar  + (long)r1*_lda + c1*8); \
        if (NS == 3) {                                                             \
            const bf16* _alr = _al + blkm * _lda + _kc;                            \
            cp16(_bs + 10240 + (uint32_t)(r0*LDSB + c0*16), _alr + (long)r0*_lda + c0*8); \
            cp16(_bs + 10240 + (uint32_t)(r1*LDSB + c1*16), _alr + (long)r1*_lda + c1*8); \
        }                                                                          \
        cp16(_bs + 20480 + (uint32_t)(r0*LDSB + c0*16), _br  + (long)r0*K + c0*8);    \
        cp16(_bs + 20480 + (uint32_t)(r1*LDSB + c1*16), _br  + (long)r1*K + c1*8);    \
        if (NS >= 2) {                                                             \
            const bf16* _blr = Bl + blkn * (long)K + _k0;                          \
            cp16(_bs + 30720 + (uint32_t)(r0*LDSB + c0*16), _blr + (long)r0*K + c0*8);    \
            cp16(_bs + 30720 + (uint32_t)(r1*LDSB + c1*16), _blr + (long)r1*K + c1*8);    \
        }                                                                          \
        CP_COMMIT();                                                               \
    } while (0)

    LOAD_STAGE(0);
    if (NIT > 1) LOAD_STAGE(1);

    const uint32_t a_off = (uint32_t)((wm*32 + (lane & 15)) * LDSB + (lane >> 4) * 16);
    const uint32_t b_off = (uint32_t)((wn*64 + ((lane >> 4) << 3) + (lane & 7)) * LDSB
                                      + ((lane >> 3) & 1) * 16);

    for (int it = 0; it < NIT; it++) {
        if (it + 1 < NIT) CP_WAIT(1); else CP_WAIT(0);
        __syncthreads();
        const uint32_t base = sb + (uint32_t)(it % 3) * STG;
#pragma unroll
        for (int kk = 0; kk < 2; kk++) {
            const uint32_t ka = base + a_off + kk * 32;
            const uint32_t kb = base + b_off + kk * 32;
            uint32_t AH[2][4], AL[2][4], BH[4][4], BL[4][4];
            LDM4(AH[0], ka);
            LDM4(AH[1], ka + 16 * LDSB);
            if (NS == 3) {
                LDM4(AL[0], ka + 10240);
                LDM4(AL[1], ka + 10240 + 16 * LDSB);
            }
#pragma unroll
            for (int p = 0; p < 4; p++) {
                LDM4(BH[p], kb + 20480 + p * 16 * LDSB);
                if (NS >= 2) LDM4(BL[p], kb + 30720 + p * 16 * LDSB);
            }
#pragma unroll
            for (int mf = 0; mf < 2; mf++)
#pragma unroll
                for (int nf = 0; nf < 8; nf++) {
                    const uint32_t* bh = &BH[nf >> 1][(nf & 1) * 2];
                    mma16816(acc[mf][nf], AH[mf], bh);
                    if (NS >= 2) {
                        const uint32_t* bl = &BL[nf >> 1][(nf & 1) * 2];
                        mma16816(acc[mf][nf], AH[mf], bl);
                    }
                    if (NS == 3) mma16816(acc[mf][nf], AL[mf], bh);
                }
        }
        if (it + 2 < NIT) LOAD_STAGE(it + 2);
    }

#pragma unroll
    for (int mf = 0; mf < 2; mf++) {
        const long m0 = blkm + wm * 32 + mf * 16 + (lane >> 2);
#pragma unroll
        for (int nf = 0; nf < 8; nf++) {
            const long n0 = blkn + wn * 64 + nf * 8 + (lane & 3) * 2;
            float b0 = bias ? bias[n0]     : 0.f;
            float b1 = bias ? bias[n0 + 1] : 0.f;
            float2 v0, v1;
            v0.x = acc[mf][nf][0] * scale + b0;
            v0.y = acc[mf][nf][1] * scale + b1;
            v1.x = acc[mf][nf][2] * scale + b0;
            v1.y = acc[mf][nf][3] * scale + b1;
            if (Cb) {
                *(uint32_t*)(Cb + m0 * (long)N + n0)       = packbf(v0.x, v0.y);
                *(uint32_t*)(Cb + (m0 + 8) * (long)N + n0) = packbf(v1.x, v1.y);
            } else {
                *(float2*)(C + m0 * (long)N + n0)       = v0;
                *(float2*)(C + (m0 + 8) * (long)N + n0) = v1;
                if (HiO) {
                    __nv_bfloat162 h0, h1, l0, l1;
                    h0.x = __float2bfloat16(v0.x); h0.y = __float2bfloat16(v0.y);
                    h1.x = __float2bfloat16(v1.x); h1.y = __float2bfloat16(v1.y);
                    l0.x = __float2bfloat16(v0.x - __bfloat162float(h0.x));
                    l0.y = __float2bfloat16(v0.y - __bfloat162float(h0.y));
                    l1.x = __float2bfloat16(v1.x - __bfloat162float(h1.x));
                    l1.y = __float2bfloat16(v1.y - __bfloat162float(h1.y));
                    *(__nv_bfloat162*)(HiO + m0 * (long)N + n0)       = h0;
                    *(__nv_bfloat162*)(HiO + (m0 + 8) * (long)N + n0) = h1;
                    *(__nv_bfloat162*)(LoO + m0 * (long)N + n0)       = l0;
                    *(__nv_bfloat162*)(LoO + (m0 + 8) * (long)N + n0) = l1;
                }
            }
        }
    }
#undef LOAD_STAGE
}

// ======================= fused flash attention ===================================
// 128 query rows per CTA; stream S in 64-slot tiles; scores NS=2 (q_hi x K hi+lo);
// online softmax; P split in registers; PV NS=3 (Ph*Vh + Ph*Vl + Pl*Vh).
#define LDQ 528
#define LDK 528
#define LDV 144
#define OQ  0
#define OKH 67584
#define OKL 101376
#define OVH 135168
#define OVL 172032
#define FA_SMEM 208896

#define LOADK(S0) do {                                                      \
        const bf16* _kh = Kh + (long)(S0) * HDIM;                           \
        const bf16* _kl = Kl + (long)(S0) * HDIM;                           \
        _Pragma("unroll")                                                   \
        for (int _i = 0; _i < 8; _i++) {                                    \
            int _idx = tid + (_i << 8);                                     \
            int _r = _idx >> 5, _c = _idx & 31;                             \
            cp16(sb + OKH + (uint32_t)(_r * LDK + _c * 16), _kh + (long)_r * HDIM + _c * 8); \
            cp16(sb + OKL + (uint32_t)(_r * LDK + _c * 16), _kl + (long)_r * HDIM + _c * 8); \
        }                                                                   \
        CP_COMMIT();                                                        \
    } while (0)

#define LOADV(S0) do {                                                      \
        _Pragma("unroll")                                                   \
        for (int _i = 0; _i < 8; _i++) {                                    \
            int _idx = tid + (_i << 8);                                     \
            int _r = _idx >> 3, _c = _idx & 7;                              \
            cp16(sb + OVH + (uint32_t)(_r * LDV + _c * 16), Vth + (long)_r * SLOTS + (S0) + _c * 8); \
            cp16(sb + OVL + (uint32_t)(_r * LDV + _c * 16), Vtl + (long)_r * SLOTS + (S0) + _c * 8); \
        }                                                                   \
        CP_COMMIT();                                                        \
    } while (0)

__global__ __launch_bounds__(256, 1)
void attn_fused(const bf16* __restrict__ Q, const bf16* __restrict__ Kh,
                const bf16* __restrict__ Kl, const bf16* __restrict__ Vth,
                const bf16* __restrict__ Vtl,
                float* __restrict__ MO, bf16* __restrict__ MOh,
                bf16* __restrict__ MOl, float* __restrict__ surp)
{
    extern __shared__ __align__(128) char smx[];
    const uint32_t sb = smem_u32(smx);
    const int tid = threadIdx.x, lane = tid & 31, wid = tid >> 5;
    const long row0 = (long)blockIdx.x * 128;

    // Q tile 128x256 (hi)
    {
        const bf16* qsrc = Q + row0 * HDIM;
#pragma unroll
        for (int i = 0; i < 16; i++) {
            int idx = tid + (i << 8);
            int r = idx >> 5, c = idx & 31;
            cp16(sb + OQ + (uint32_t)(r * LDQ + c * 16), qsrc + (long)r * HDIM + c * 8);
        }
        CP_COMMIT();
    }
    LOADK(0);
    LOADV(0);

    const uint32_t a_off  = sb + OQ + (uint32_t)((wid * 16 + (lane & 15)) * LDQ + (lane >> 4) * 16);
    const uint32_t bk_off = (uint32_t)(((((lane >> 4) << 3) + (lane & 7)) * LDK) + ((lane >> 3) & 1) * 16);
    const uint32_t bv_off = (uint32_t)(((((lane >> 4) << 3) + (lane & 7)) * LDV) + ((lane >> 3) & 1) * 16);

    float oacc[32][4];
#pragma unroll
    for (int i = 0; i < 32; i++)
#pragma unroll
        for (int j = 0; j < 4; j++) oacc[i][j] = 0.f;
    float m0 = -INFINITY, m1 = -INFINITY, l0 = 0.f, l1 = 0.f;

    for (int s = 0; s < 64; s++) {
        CP_WAIT(1);                              // K_s resident
        __syncthreads();

        float sacc[8][4];
#pragma unroll
        for (int nf = 0; nf < 8; nf++)
#pragma unroll
            for (int j = 0; j < 4; j++) sacc[nf][j] = 0.f;

#pragma unroll 4
        for (int kk = 0; kk < 16; kk++) {
            uint32_t A[4], BH[4][4], BL[4][4];
            LDM4(A, a_off + kk * 32);
#pragma unroll
            for (int p = 0; p < 4; p++) {
                LDM4(BH[p], sb + OKH + bk_off + (uint32_t)(p * 16 * LDK) + kk * 32);
                LDM4(BL[p], sb + OKL + bk_off + (uint32_t)(p * 16 * LDK) + kk * 32);
            }
#pragma unroll
            for (int nf = 0; nf < 8; nf++) {
                mma16816(sacc[nf], A, &BH[nf >> 1][(nf & 1) * 2]);
                mma16816(sacc[nf], A, &BL[nf >> 1][(nf & 1) * 2]);
            }
        }
        __syncthreads();                         // all warps done reading K
        LOADK(s + 1 < 64 ? (s + 1) * 64 : 0);    // prefetch next K

        // --- online softmax update (scale 1/16) ---
        float tm0 = -INFINITY, tm1 = -INFINITY;
#pragma unroll
        for (int nf = 0; nf < 8; nf++) {
            tm0 = fmaxf(tm0, fmaxf(sacc[nf][0], sacc[nf][1]));
            tm1 = fmaxf(tm1, fmaxf(sacc[nf][2], sacc[nf][3]));
        }
        tm0 = fmaxf(tm0, __shfl_xor_sync(0xffffffffu, tm0, 1));
        tm0 = fmaxf(tm0, __shfl_xor_sync(0xffffffffu, tm0, 2));
        tm1 = fmaxf(tm1, __shfl_xor_sync(0xffffffffu, tm1, 1));
        tm1 = fmaxf(tm1, __shfl_xor_sync(0xffffffffu, tm1, 2));
        tm0 *= 0.0625f; tm1 *= 0.0625f;
        const float nm0 = fmaxf(m0, tm0), nm1 = fmaxf(m1, tm1);
        const float al0 = expf(m0 - nm0),  al1 = expf(m1 - nm1);

        uint32_t PH[4][4], PL[4][4];
        float ls0 = 0.f, ls1 = 0.f;
#pragma unroll
        for (int nf = 0; nf < 8; nf++) {
            float p0 = expf(fmaf(sacc[nf][0], 0.0625f, -nm0));
            float p1 = expf(fmaf(sacc[nf][1], 0.0625f, -nm0));
            float p2 = expf(fmaf(sacc[nf][2], 0.0625f, -nm1));
            float p3 = expf(fmaf(sacc[nf][3], 0.0625f, -nm1));
            ls0 += p0 + p1; ls1 += p2 + p3;
            float h0 = __bfloat162float(__float2bfloat16(p0));
            float h1 = __bfloat162float(__float2bfloat16(p1));
            float h2 = __bfloat162float(__float2bfloat16(p2));
            float h3 = __bfloat162float(__float2bfloat16(p3));
            const int kc = nf >> 1, bi = (nf & 1) * 2;
            PH[kc][bi]     = packbf(h0, h1);
            PH[kc][bi + 1] = packbf(h2, h3);
            PL[kc][bi]     = packbf(p0 - h0, p1 - h1);
            PL[kc][bi + 1] = packbf(p2 - h2, p3 - h3);
        }
        ls0 += __shfl_xor_sync(0xffffffffu, ls0, 1);
        ls0 += __shfl_xor_sync(0xffffffffu, ls0, 2);
        ls1 += __shfl_xor_sync(0xffffffffu, ls1, 1);
        ls1 += __shfl_xor_sync(0xffffffffu, ls1, 2);
        l0 = l0 * al0 + ls0;
        l1 = l1 * al1 + ls1;
        m0 = nm0; m1 = nm1;
#pragma unroll
        for (int i = 0; i < 32; i++) {
            oacc[i][0] *= al0; oacc[i][1] *= al0;
            oacc[i][2] *= al1; oacc[i][3] *= al1;
        }

        CP_WAIT(1);                              // V_s resident
        __syncthreads();
#pragma unroll
        for (int kc = 0; kc < 4; kc++) {
#pragma unroll
            for (int g = 0; g < 16; g++) {
                uint32_t VH[4], VL[4];
                LDM4(VH, sb + OVH + bv_off + (uint32_t)(g * 16 * LDV) + kc * 32);
                LDM4(VL, sb + OVL + bv_off + (uint32_t)(g * 16 * LDV) + kc * 32);
                mma16816(oacc[2*g],     PH[kc], &VH[0]);
                mma16816(oacc[2*g],     PH[kc], &VL[0]);
                mma16816(oacc[2*g],     PL[kc], &VH[0]);
                mma16816(oacc[2*g + 1], PH[kc], &VH[2]);
                mma16816(oacc[2*g + 1], PH[kc], &VL[2]);
                mma16816(oacc[2*g + 1], PL[kc], &VH[2]);
            }
        }
        __syncthreads();                         // all warps done reading V
        LOADV(s + 1 < 64 ? (s + 1) * 64 : 0);    // prefetch next V
    }
    CP_WAIT(0);

    const float inv0 = 1.f / l0, inv1 = 1.f / l1;
    const long gr0 = row0 + wid * 16 + (lane >> 2);
    const long gr1 = gr0 + 8;
#pragma unroll
    for (int nf2 = 0; nf2 < 32; nf2++) {
        const int c = nf2 * 8 + (lane & 3) * 2;
        float2 v0, v1;
        v0.x = oacc[nf2][0] * inv0; v0.y = oacc[nf2][1] * inv0;
        v1.x = oacc[nf2][2] * inv1; v1.y = oacc[nf2][3] * inv1;
        *(float2*)(MO + gr0 * HDIM + c) = v0;
        *(float2*)(MO + gr1 * HDIM + c) = v1;
        float h0 = __bfloat162float(__float2bfloat16(v0.x));
        float h1 = __bfloat162float(__float2bfloat16(v0.y));
        float h2 = __bfloat162float(__float2bfloat16(v1.x));
        float h3 = __bfloat162float(__float2bfloat16(v1.y));
        *(uint32_t*)(MOh + gr0 * HDIM + c) = packbf(h0, h1);
        *(uint32_t*)(MOh + gr1 * HDIM + c) = packbf(h2, h3);
        *(uint32_t*)(MOl + gr0 * HDIM + c) = packbf(v0.x - h0, v0.y - h1);
        *(uint32_t*)(MOl + gr1 * HDIM + c) = packbf(v1.x - h2, v1.y - h3);
    }
    if ((lane & 3) == 0) {
        surp[gr0] = 1.f - inv0;
        surp[gr1] = 1.f - inv1;
    }
}

// ======================= split conversions ======================================
__global__ void conv_split(const float* __restrict__ src, long sstride, int Cc, long total,
                           bf16* __restrict__ hi, bf16* __restrict__ lo)
{
    long i = (long)blockIdx.x * 256 + threadIdx.x;
    if (i >= total) return;
    long r = i / Cc; int cc = (int)(i - r * Cc);
    float v = src[r * sstride + cc];
    bf16 h = __float2bfloat16(v);
    hi[i] = h;
    lo[i] = __float2bfloat16(v - __bfloat162float(h));
}

__global__ void conv_split_T(const float* __restrict__ src, int R, int Cc,
                             bf16* __restrict__ hi, bf16* __restrict__ lo)
{
    long i = (long)blockIdx.x * 256 + threadIdx.x;
    if (i >= (long)R * Cc) return;
    int r = (int)(i / Cc), cc = (int)(i - (long)r * Cc);
    float v = src[i];
    bf16 h = __float2bfloat16(v);
    long o = (long)cc * R + r;
    hi[o] = h;
    lo[o] = __float2bfloat16(v - __bfloat162float(h));
}

// ======================= reductions ==============================================
__device__ __forceinline__ float block_sum_256(float v, float* red)
{
#pragma unroll
    for (int o = 16; o > 0; o >>= 1) v += __shfl_xor_sync(0xffffffffu, v, o);
    if ((threadIdx.x & 31) == 0) red[threadIdx.x >> 5] = v;
    __syncthreads();
    float t = 0.f;
#pragma unroll
    for (int i = 0; i < 8; i++) t += red[i];
    __syncthreads();
    return t;
}
__device__ __forceinline__ float block_max_256(float v, float* red)
{
#pragma unroll
    for (int o = 16; o > 0; o >>= 1) v = fmaxf(v, __shfl_xor_sync(0xffffffffu, v, o));
    if ((threadIdx.x & 31) == 0) red[threadIdx.x >> 5] = v;
    __syncthreads();
    float t = -INFINITY;
#pragma unroll
    for (int i = 0; i < 8; i++) t = fmaxf(t, red[i]);
    __syncthreads();
    return t;
}

// ======================= elementwise / epilogue kernels =========================
__global__ void zero_kernel()
{
    int i = blockIdx.x * blockDim.x + threadIdx.x;
    if (i < SLOTS*HDIM) { g_gk[i] = 0.f; g_gv[i] = 0.f; }
    if (i < SLOTS) g_gcnt[i] = 0.f;
}

__global__ __launch_bounds__(256)
void ln_gelu_q(const float* __restrict__ X, const float* __restrict__ gm,
               const float* __restrict__ bt, bf16* __restrict__ hi)
{
    __shared__ float red[8];
    const long row = blockIdx.x; const int tid = threadIdx.x;
    float v    = X[row * HDIM + tid];
    float mean = block_sum_256(v, red) * (1.f / 256.f);
    float d    = v - mean;
    float var  = block_sum_256(d * d, red) * (1.f / 256.f);
    float t    = d * rsqrtf(var + 1e-5f) * gm[tid] + bt[tid];
    float g    = 0.5f * t * (1.f + erff(t * 0.70710678f));
    hi[row * HDIM + tid] = __float2bfloat16(g);
}

__global__ __launch_bounds__(256)
void ln_gelu_kv(float* __restrict__ X, const float* __restrict__ gm,
                const float* __restrict__ bt, bf16* __restrict__ knh,
                float* __restrict__ lr)
{
    __shared__ float red[8];
    const long row = blockIdx.x; const int tid = threadIdx.x;
    float* xr = X + row * KVW;
    float vals[3];
    float s = 0.f;
#pragma unroll
    for (int i = 0; i < 3; i++) { vals[i] = xr[tid + (i << 8)]; s += vals[i]; }
    float mean = block_sum_256(s, red) * (1.f / 768.f);
    float sq = 0.f;
#pragma unroll
    for (int i = 0; i < 3; i++) { float d = vals[i] - mean; sq += d * d; }
    float var  = block_sum_256(sq, red) * (1.f / 768.f);
    float rstd = rsqrtf(var + 1e-5f);
    float gout[3];
#pragma unroll
    for (int i = 0; i < 3; i++) {
        int c = tid + (i << 8);
        float t = (vals[i] - mean) * rstd * gm[c] + bt[c];
        gout[i] = 0.5f * t * (1.f + erff(t * 0.70710678f));
        xr[c] = gout[i];
    }
    knh[row * HDIM + tid] = __float2bfloat16(gout[0]);
    float sg = 1.f / (1.f + expf(-gout[2]));
    float tot = block_sum_256(sg, red);
    if (tid == 0) lr[row] = tot * (1.f / 256.f);
}

__global__ void memupd_kernel(const float* __restrict__ Km, const float* __restrict__ Vm,
                              float* __restrict__ Kout, float* __restrict__ Vout)
{
    int i = blockIdx.x * blockDim.x + threadIdx.x;
    float cnt = g_gcnt[i >> 8];
    float k = Km[i], v = Vm[i];
    Kout[i] = k + 0.1f * (g_gk[i] - cnt * k);
    Vout[i] = v + 0.1f * (g_gv[i] - cnt * v);
}

__global__ __launch_bounds__(256)
void final_ln_kernel(const float* __restrict__ opre, const float* __restrict__ xproj,
                     const float* __restrict__ go, const float* __restrict__ beo,
                     const float* __restrict__ g1, const float* __restrict__ be1,
                     float* __restrict__ out)
{
    __shared__ float red[8];
    const int row = blockIdx.x, tid = threadIdx.x;
    float v    = opre[(size_t)row * HDIM + tid];
    float mean = block_sum_256(v, red) * (1.f / 256.f);
    float d    = v - mean;
    float var  = block_sum_256(d * d, red) * (1.f / 256.f);
    float t    = d * rsqrtf(var + 1e-5f) * go[tid] + beo[tid];
    float u    = t + xproj[(size_t)row * HDIM + tid];
    float m2   = block_sum_256(u, red) * (1.f / 256.f);
    float d2   = u - m2;
    float v2   = block_sum_256(d2 * d2, red) * (1.f / 256.f);
    out[(size_t)row * HDIM + tid] = d2 * rsqrtf(v2 + 1e-5f) * g1[tid] + be1[tid];
}

// ======================= exact argmax + gated scatter ===========================
__global__ __launch_bounds__(256)
void argmax_scatter(const bf16* __restrict__ wsim, const float* __restrict__ kvbuf,
                    const float* __restrict__ Km, const float* __restrict__ surp)
{
    __shared__ float red[8];
    __shared__ int s_cnt;
    __shared__ int s_cand[128];
    const long row = blockIdx.x;
    const int tid = threadIdx.x;
    const bf16* wr = wsim + row * SLOTS;
    float v[16], mloc = -INFINITY;
#pragma unroll
    for (int i = 0; i < 16; i++) {
        v[i] = __bfloat162float(wr[tid + (i << 8)]);
        mloc = fmaxf(mloc, v[i]);
    }
    float m = block_max_256(mloc, red);
    if (tid == 0) s_cnt = 0;
    __syncthreads();
#pragma unroll
    for (int i = 0; i < 16; i++) {
        if (v[i] >= m - 1e-1f) {                 // window covers bf16 MMA + storage error
            int p = atomicAdd(&s_cnt, 1);
            if (p < 128) s_cand[p] = tid + (i << 8);
        }
    }
    __syncthreads();
    int n = s_cnt < 128 ? s_cnt : 128;
    const float kn = kvbuf[row * KVW + tid];
    float bestv = -INFINITY; int besti = 0x7fffffff;
    for (int j = 0; j < n; j++) {
        int slot = s_cand[j];
        float s = block_sum_256(kn * Km[(long)slot * HDIM + tid], red);  // exact fp32 rescore
        if (s > bestv || (s == bestv && slot < besti)) { bestv = s; besti = slot; }
    }
    float gate = surp[row];
    atomicAdd(&g_gk[(long)besti * HDIM + tid], gate * kn);
    atomicAdd(&g_gv[(long)besti * HDIM + tid], gate * kvbuf[row * KVW + HDIM + tid]);
    if (tid == 0) atomicAdd(&g_gcnt[besti], gate);
}

// =================================================================================
extern "C" void kernel_launch(void* const* d_in, const int* in_sizes, int n_in,
                              void* d_out, int out_size)
{
    const float* x    = (const float*)d_in[0];
    const float* W_in = (const float*)d_in[1];
    const float* b_in = (const float*)d_in[2];
    const float* W_q  = (const float*)d_in[3];
    const float* b_q  = (const float*)d_in[4];
    const float* gq   = (const float*)d_in[5];
    const float* beq  = (const float*)d_in[6];
    const float* Km   = (const float*)d_in[7];
    const float* Vm   = (const float*)d_in[8];
    const float* W_kv = (const float*)d_in[9];
    const float* b_kv = (const float*)d_in[10];
    const float* gkv  = (const float*)d_in[11];
    const float* bekv = (const float*)d_in[12];
    const float* W_o  = (const float*)d_in[13];
    const float* b_o  = (const float*)d_in[14];
    const float* go   = (const float*)d_in[15];
    const float* beo  = (const float*)d_in[16];
    const float* g1   = (const float*)d_in[17];
    const float* be1  = (const float*)d_in[18];

    float* out    = (float*)d_out;
    float* o_out  = out;
    float* k_out  = out + 8388608;
    float* v_out  = out + 9437184;
    float* s_out  = out + 10485760;
    float* lr_out = out + 10518528;

    float *p_xproj, *p_query, *p_memout, *p_kvbuf, *p_opre;
    cudaGetSymbolAddress((void**)&p_xproj,  g_xproj);
    cudaGetSymbolAddress((void**)&p_query,  g_query);
    cudaGetSymbolAddress((void**)&p_memout, g_memout);
    cudaGetSymbolAddress((void**)&p_kvbuf,  g_kvbuf);
    cudaGetSymbolAddress((void**)&p_opre,   g_opre);
    bf16 *wsb,*xh,*xl,*xph,*xpl,*qh,*moh,*mol,*knh;
    bf16 *kmh,*kml,*vth,*vtl,*winh,*winl,*wqh,*wql,*wkvh,*wkvl,*woh,*wol;
    cudaGetSymbolAddress((void**)&wsb, g_wsb);
    cudaGetSymbolAddress((void**)&xh,  g_xh);  cudaGetSymbolAddress((void**)&xl,  g_xl);
    cudaGetSymbolAddress((void**)&xph, g_xph); cudaGetSymbolAddress((void**)&xpl, g_xpl);
    cudaGetSymbolAddress((void**)&qh,  g_qh);
    cudaGetSymbolAddress((void**)&moh, g_moh); cudaGetSymbolAddress((void**)&mol, g_mol);
    cudaGetSymbolAddress((void**)&knh, g_knh);
    cudaGetSymbolAddress((void**)&kmh, g_kmh); cudaGetSymbolAddress((void**)&kml, g_kml);
    cudaGetSymbolAddress((void**)&vth, g_vth); cudaGetSymbolAddress((void**)&vtl, g_vtl);
    cudaGetSymbolAddress((void**)&winh,g_winh);cudaGetSymbolAddress((void**)&winl,g_winl);
    cudaGetSymbolAddress((void**)&wqh, g_wqh); cudaGetSymbolAddress((void**)&wql, g_wql);
    cudaGetSymbolAddress((void**)&wkvh,g_wkvh);cudaGetSymbolAddress((void**)&wkvl,g_wkvl);
    cudaGetSymbolAddress((void**)&woh, g_woh); cudaGetSymbolAddress((void**)&wol, g_wol);

    cudaFuncSetAttribute(gemm_bf16s<3>, cudaFuncAttributeMaxDynamicSharedMemorySize, GSMEM);
    cudaFuncSetAttribute(gemm_bf16s<1>, cudaFuncAttributeMaxDynamicSharedMemorySize, GSMEM);
    cudaFuncSetAttribute(attn_fused,    cudaFuncAttributeMaxDynamicSharedMemorySize, FA_SMEM);

    const long NTOKH = (long)MTOK * HDIM;

    zero_kernel<<<4096, 256>>>();

    // weight / memory conversions (B operands are [N][K] row-major)
    conv_split_T<<<(256*256+255)/256, 256>>>(W_in, 256, 256, winh, winl);
    conv_split_T<<<(256*256+255)/256, 256>>>(W_q,  256, 256, wqh,  wql);
    conv_split_T<<<(512*768+255)/256, 256>>>(W_kv, 512, 768, wkvh, wkvl);
    conv_split_T<<<(512*256+255)/256, 256>>>(W_o,  512, 256, woh,  wol);
    conv_split  <<<(SLOTS*HDIM+255)/256, 256>>>(Km, 256, 256, (long)SLOTS*HDIM, kmh, kml);
    conv_split_T<<<(SLOTS*HDIM+255)/256, 256>>>(Vm, SLOTS, 256, vth, vtl);
    conv_split  <<<(NTOKH+255)/256, 256>>>(x, 256, 256, NTOKH, xh, xl);

    // x_proj = x @ W_in + b_in  (fused split out)
    gemm_bf16s<3><<<dim3(2,256), 256, GSMEM>>>(xh, xl, 256, xh, xl, 256, 256, 256,
                                               winh, winl, b_in, 1.f, p_xproj, 256, xph, xpl, nullptr);

    // query = gelu(LN(x_proj @ W_q + b_q))  -> qh (hi only)
    gemm_bf16s<3><<<dim3(2,256), 256, GSMEM>>>(xph, xpl, 256, xph, xpl, 256, 256, 256,
                                               wqh, wql, b_q, 1.f, p_query, 256, nullptr, nullptr, nullptr);
    ln_gelu_q<<<32768, 256>>>(p_query, gq, beq, qh);

    // fused: sim -> softmax -> mem_out (+ hi/lo splits, surprise)
    attn_fused<<<256, 256, FA_SMEM>>>(qh, kmh, kml, vth, vtl, p_memout, moh, mol, s_out);

    // kv_lr = gelu(LN(concat(x_proj, mem_out) @ W_kv + b_kv)) ; knh + lr fused
    gemm_bf16s<3><<<dim3(6,256), 256, GSMEM>>>(xph, xpl, 256, moh, mol, 256, 256, 512,
                                               wkvh, wkvl, b_kv, 1.f, p_kvbuf, 768, nullptr, nullptr, nullptr);
    ln_gelu_kv<<<32768, 256>>>(p_kvbuf, gkv, bekv, knh, lr_out);

    // wsim = key_new @ K_mem^T  (NS=1, bf16 out), then exact argmax + scatter
    gemm_bf16s<1><<<dim3(32,256), 256, GSMEM>>>(knh, nullptr, 256, knh, nullptr, 256, 256, 256,
                                                kmh, nullptr, nullptr, 1.f, nullptr, SLOTS, nullptr, nullptr, wsb);
    argmax_scatter<<<32768, 256>>>(wsb, p_kvbuf, Km, s_out);
    memupd_kernel<<<4096, 256>>>(Km, Vm, k_out, v_out);

    // out = LN(LN(combined @ W_o + b_o) + x_proj)
    gemm_bf16s<3><<<dim3(2,256), 256, GSMEM>>>(xph, xpl, 256, moh, mol, 256, 256, 512,
                                               woh, wol, b_o, 1.f, p_opre, 256, nullptr, nullptr, nullptr);
    final_ln_kernel<<<32768, 256>>>(p_opre, p_xproj, go, beo, g1, be1, o_out);
}